// round 13
// baseline (speedup 1.0000x reference)
#include <cuda_runtime.h>
#include <cuda_fp16.h>
#include <stdint.h>

// Problem constants
static constexpr int Bb = 8;
static constexpr int Ss = 2048;
static constexpr int Dd = 1024;
static constexpr int MT = Bb * Ss;
static constexpr float INV_TEMP = 1.0f / 32.0f;

// GEMM tiling: 128(M) x 64(N) x 64(K) stages, 2-stage cp.async pipeline.
// 128 threads / 4 warps per CTA, warp tile 64x32, 4 CTAs per SM (RF cap).
#define STAGE_SZ 24576           // A tile 16KB + B tile 8KB
#define SMEMSZ   49152           // 2 stages
#define NT 128

// fp16 scratch (device globals: allocation-free)
__device__ __half g_qx[(size_t)MT * Dd];
__device__ __half g_kx[(size_t)MT * Dd];
__device__ __half g_vx[(size_t)MT * Dd];
__device__ __half g_wq[(size_t)Dd * Dd];
__device__ __half g_wk[(size_t)Dd * Dd];
__device__ __half g_wv[(size_t)Dd * Dd];
__device__ __half g_qp[(size_t)MT * Dd];
__device__ __half g_kp[(size_t)MT * Dd];
__device__ __half g_vp[(size_t)MT * Dd];
__device__ __half g_attn_h[(size_t)Bb * Ss * Ss];  // fp16 softmax output

// ---------------------------------------------------------------------------
// PTX helpers
// ---------------------------------------------------------------------------
__device__ __forceinline__ uint32_t smem_u32(const void* p) {
    return (uint32_t)__cvta_generic_to_shared(p);
}
__device__ __forceinline__ uint32_t swz(uint32_t off) {
    return off ^ ((off >> 3) & 0x70);   // SW128 for 128B rows
}
__device__ __forceinline__ void cp16(uint32_t dst, const void* src) {
    asm volatile("cp.async.cg.shared.global [%0], [%1], 16;" :: "r"(dst), "l"(src));
}
__device__ __forceinline__ void ldsm4(uint32_t& r0, uint32_t& r1,
                                      uint32_t& r2, uint32_t& r3, uint32_t addr) {
    asm volatile("ldmatrix.sync.aligned.m8n8.x4.shared.b16 {%0,%1,%2,%3}, [%4];"
                 : "=r"(r0), "=r"(r1), "=r"(r2), "=r"(r3) : "r"(addr));
}
__device__ __forceinline__ void ldsm4t(uint32_t& r0, uint32_t& r1,
                                       uint32_t& r2, uint32_t& r3, uint32_t addr) {
    asm volatile("ldmatrix.sync.aligned.m8n8.x4.trans.shared.b16 {%0,%1,%2,%3}, [%4];"
                 : "=r"(r0), "=r"(r1), "=r"(r2), "=r"(r3) : "r"(addr));
}
__device__ __forceinline__ void mma16816(float c[4], const uint32_t a[4],
                                         const uint32_t b[2]) {
    asm volatile(
        "mma.sync.aligned.m16n8k16.row.col.f32.f16.f16.f32 "
        "{%0,%1,%2,%3}, {%4,%5,%6,%7}, {%8,%9}, {%0,%1,%2,%3};"
        : "+f"(c[0]), "+f"(c[1]), "+f"(c[2]), "+f"(c[3])
        : "r"(a[0]), "r"(a[1]), "r"(a[2]), "r"(a[3]), "r"(b[0]), "r"(b[1]));
}

// ---------------------------------------------------------------------------
// Stage loader. A: 128 rows x 64 k-cols (row-major, advance cols by kt).
// B (NT):     64 n-rows x 64 k-cols (row-major [n][k], advance cols by kt).
// B (TRANS):  64 k-rows x 64 n-cols (row-major [k][n], advance ROWS by kt).
// ---------------------------------------------------------------------------
template <int LDA, int LDB, bool BTRANS>
__device__ __forceinline__ void issue_stage(
    const __half* __restrict__ A, const __half* __restrict__ B, int kt,
    uint32_t abase, uint32_t bbase, int tid)
{
#pragma unroll
    for (int i = 0; i < 8; i++) {
        const int id = tid + i * NT;
        const int row = id >> 3, cc = id & 7;
        cp16(abase + swz(row * 128 + cc * 16), A + (size_t)row * LDA + kt + cc * 8);
    }
#pragma unroll
    for (int i = 0; i < 4; i++) {
        const int id = tid + i * NT;
        const int row = id >> 3, cc = id & 7;
        const __half* src = BTRANS
            ? B + (size_t)(kt + row) * LDB + cc * 8
            : B + (size_t)row * LDB + kt + cc * 8;
        cp16(bbase + swz(row * 128 + cc * 16), src);
    }
    asm volatile("cp.async.commit_group;");
}

// ---------------------------------------------------------------------------
// Compute one 128x64x64 stage. Warp grid 2(m) x 2(n); warp tile 64x32.
// ---------------------------------------------------------------------------
template <bool BTRANS>
__device__ __forceinline__ void compute_stage(
    uint32_t abase, uint32_t bbase, int wm, int wn, int lane,
    float acc[4][4][4])
{
    const int a_row = wm * 64 + (lane & 15);
    const int a_col = (lane >> 4) * 8;
    // NT path lane mapping
    const int b_row = wn * 32 + ((lane >> 4) * 8) + (lane & 7);
    const int b_col = ((lane >> 3) & 1) * 8;
    // TRANS path lane mapping: row = k (lane&15), col-block = (lane>>4)*8
    const int bt_k = lane & 15;
    const int bt_n = wn * 32 + (lane >> 4) * 8;
#pragma unroll
    for (int ks = 0; ks < 4; ks++) {
        uint32_t af[4][4], bf[4][2];
#pragma unroll
        for (int mi = 0; mi < 4; mi++)
            ldsm4(af[mi][0], af[mi][1], af[mi][2], af[mi][3],
                  abase + swz(((a_row + mi * 16) << 7) + (ks * 16 + a_col) * 2));
#pragma unroll
        for (int nj = 0; nj < 2; nj++) {
            if (BTRANS) {
                ldsm4t(bf[2 * nj][0], bf[2 * nj][1],
                       bf[2 * nj + 1][0], bf[2 * nj + 1][1],
                       bbase + swz(((ks * 16 + bt_k) << 7) + (bt_n + nj * 16) * 2));
            } else {
                ldsm4(bf[2 * nj][0], bf[2 * nj][1],
                      bf[2 * nj + 1][0], bf[2 * nj + 1][1],
                      bbase + swz(((b_row + nj * 16) << 7) + (ks * 16 + b_col) * 2));
            }
        }
#pragma unroll
        for (int mi = 0; mi < 4; mi++)
#pragma unroll
            for (int ni = 0; ni < 4; ni++)
                mma16816(acc[mi][ni], af[mi], bf[ni]);
    }
}

// ---------------------------------------------------------------------------
// Full GEMM mainloop. 2-stage pipeline.
// ---------------------------------------------------------------------------
template <int LDA, int LDB, bool BTRANS>
__device__ __forceinline__ void gemm_main(
    const __half* __restrict__ A, const __half* __restrict__ B,
    int nk, char* sm, float acc[4][4][4])
{
    const uint32_t smb = smem_u32(sm);
    const int tid = threadIdx.x, lane = tid & 31, warp = tid >> 5;
    const int wm = warp & 1, wn = warp >> 1;

    issue_stage<LDA, LDB, BTRANS>(A, B, 0, smb, smb + 16384, tid);

    for (int s = 0; s < nk; s++) {
        if (s + 1 < nk) {
            const uint32_t bn = smb + (uint32_t)((s + 1) & 1) * STAGE_SZ;
            issue_stage<LDA, LDB, BTRANS>(A, B, (s + 1) * 64, bn, bn + 16384, tid);
            asm volatile("cp.async.wait_group 1;");
        } else {
            asm volatile("cp.async.wait_group 0;");
        }
        __syncthreads();   // stage s visible
        const uint32_t bc = smb + (uint32_t)(s & 1) * STAGE_SZ;
        compute_stage<BTRANS>(bc, bc + 16384, wm, wn, lane, acc);
        __syncthreads();   // all warps done with buffer s&1 before refill
    }
}

#define ZERO_ACC(acc)                             \
    float acc[4][4][4];                           \
    _Pragma("unroll") for (int i = 0; i < 4; i++) \
    _Pragma("unroll") for (int j = 0; j < 4; j++) \
    _Pragma("unroll") for (int c = 0; c < 4; c++) acc[i][j][c] = 0.0f;

// ---------------------------------------------------------------------------
// Kernel 0: fp32 -> fp16 conversions (q,k,v,Wq,Wk,Wv)
// ---------------------------------------------------------------------------
__global__ __launch_bounds__(512) void convert_kernel(
    const float* __restrict__ q, const float* __restrict__ k,
    const float* __restrict__ v, const float* __restrict__ Wq,
    const float* __restrict__ Wk, const float* __restrict__ Wv)
{
    const int z = blockIdx.z;
    const float* src;
    __half* dst;
    size_t n8;
    if (z == 0)      { src = q;  dst = g_qx; n8 = (size_t)MT * Dd / 8; }
    else if (z == 1) { src = k;  dst = g_kx; n8 = (size_t)MT * Dd / 8; }
    else if (z == 2) { src = v;  dst = g_vx; n8 = (size_t)MT * Dd / 8; }
    else if (z == 3) { src = Wq; dst = g_wq; n8 = (size_t)Dd * Dd / 8; }
    else if (z == 4) { src = Wk; dst = g_wk; n8 = (size_t)Dd * Dd / 8; }
    else             { src = Wv; dst = g_wv; n8 = (size_t)Dd * Dd / 8; }
    const size_t i = (size_t)blockIdx.x * 512 + threadIdx.x;
    if (i >= n8) return;
    const float4* s4 = (const float4*)src;
    float4 a = s4[i * 2], b = s4[i * 2 + 1];
    __half2 h[4];
    h[0] = __floats2half2_rn(a.x, a.y);
    h[1] = __floats2half2_rn(a.z, a.w);
    h[2] = __floats2half2_rn(b.x, b.y);
    h[3] = __floats2half2_rn(b.z, b.w);
    ((uint4*)dst)[i] = *(uint4*)h;
}

// ---------------------------------------------------------------------------
// Kernel 1: QKV projections. z selects GEMM. Output fp16 (+bias).
// ---------------------------------------------------------------------------
__global__ __launch_bounds__(NT, 4) void proj_hmma(
    const float* __restrict__ bq, const float* __restrict__ bk,
    const float* __restrict__ bv)
{
    extern __shared__ char sm[];
    const int m0 = blockIdx.x * 128, n0 = blockIdx.y * 64, z = blockIdx.z;
    const __half *X, *W;
    const float* bias;
    __half* C;
    if (z == 0)      { X = g_qx; W = g_wq; bias = bq; C = g_qp; }
    else if (z == 1) { X = g_kx; W = g_wk; bias = bk; C = g_kp; }
    else             { X = g_vx; W = g_wv; bias = bv; C = g_vp; }

    ZERO_ACC(acc);
    gemm_main<Dd, Dd, false>(X + (size_t)m0 * Dd, W + (size_t)n0 * Dd, Dd / 64, sm, acc);

    const int lane = threadIdx.x & 31, warp = threadIdx.x >> 5;
    const int wm = warp & 1, wn = warp >> 1, g = lane >> 2, tk = lane & 3;
#pragma unroll
    for (int mi = 0; mi < 4; mi++) {
        const int r0 = m0 + wm * 64 + mi * 16 + g;
#pragma unroll
        for (int ni = 0; ni < 4; ni++) {
            const int col = n0 + wn * 32 + ni * 8 + tk * 2;
            const float bx = bias[col], by = bias[col + 1];
            *(__half2*)&C[(size_t)r0 * Dd + col] =
                __floats2half2_rn(acc[mi][ni][0] + bx, acc[mi][ni][1] + by);
            *(__half2*)&C[(size_t)(r0 + 8) * Dd + col] =
                __floats2half2_rn(acc[mi][ni][2] + bx, acc[mi][ni][3] + by);
        }
    }
}

// ---------------------------------------------------------------------------
// Kernel 2: causal raw scores, fp32 logits out (/32)
// ---------------------------------------------------------------------------
__global__ __launch_bounds__(NT, 4) void scores_hmma(float* __restrict__ attn) {
    const int m0 = blockIdx.x * 128, n0 = blockIdx.y * 64;
    if (n0 > m0 + 127) return;  // tile entirely above diagonal
    extern __shared__ char sm[];
    const int b = blockIdx.z;
    const __half* A = g_qp + (size_t)b * Ss * Dd;
    const __half* B = g_kp + (size_t)b * Ss * Dd;
    float* C = attn + (size_t)b * Ss * Ss;

    ZERO_ACC(acc);
    gemm_main<Dd, Dd, false>(A + (size_t)m0 * Dd, B + (size_t)n0 * Dd, Dd / 64, sm, acc);

    const int lane = threadIdx.x & 31, warp = threadIdx.x >> 5;
    const int wm = warp & 1, wn = warp >> 1, g = lane >> 2, tk = lane & 3;
#pragma unroll
    for (int mi = 0; mi < 4; mi++) {
        const int r0 = m0 + wm * 64 + mi * 16 + g;
#pragma unroll
        for (int ni = 0; ni < 4; ni++) {
            const int col = n0 + wn * 32 + ni * 8 + tk * 2;
            *(float2*)&C[(size_t)r0 * Ss + col] =
                make_float2(acc[mi][ni][0] * INV_TEMP, acc[mi][ni][1] * INV_TEMP);
            *(float2*)&C[(size_t)(r0 + 8) * Ss + col] =
                make_float2(acc[mi][ni][2] * INV_TEMP, acc[mi][ni][3] * INV_TEMP);
        }
    }
}

// ---------------------------------------------------------------------------
// Kernel 3: causal row softmax (fp32 in-place + fp16 copy).
// 512 threads, one float4 per thread; warp-shuffle reductions.
// ---------------------------------------------------------------------------
__global__ __launch_bounds__(512) void softmax_kernel(float* __restrict__ attn) {
    const int rix = blockIdx.x;
    const int b = rix / Ss;
    const int i = rix % Ss;
    float* row = attn + (size_t)b * Ss * Ss + (size_t)i * Ss;
    __half2* rowh2 = (__half2*)(g_attn_h + (size_t)b * Ss * Ss + (size_t)i * Ss);
    const int tid = threadIdx.x;
    const int lane = tid & 31, wid = tid >> 5;     // 16 warps
    const int valid = i + 1;
    const int bound = ((i >> 7) + 1) << 7;         // 128-aligned causal bound
    const int j0 = tid * 4;

    float4 x = make_float4(0.f, 0.f, 0.f, 0.f);
    float lmax = -3.0e38f;
    if (j0 < valid) {
        x = *(const float4*)(row + j0);
        float* e = (float*)&x;
#pragma unroll
        for (int c = 0; c < 4; c++)
            if (j0 + c < valid) lmax = fmaxf(lmax, e[c]);
    }

    __shared__ float sred[16];
#pragma unroll
    for (int o = 16; o > 0; o >>= 1)
        lmax = fmaxf(lmax, __shfl_xor_sync(0xFFFFFFFF, lmax, o));
    if (lane == 0) sred[wid] = lmax;
    __syncthreads();
    float mx = sred[0];
#pragma unroll
    for (int w = 1; w < 16; w++) mx = fmaxf(mx, sred[w]);

    float lsum = 0.0f;
    if (j0 < valid) {
        float* e = (float*)&x;
#pragma unroll
        for (int c = 0; c < 4; c++) {
            const float t = (j0 + c < valid) ? __expf(e[c] - mx) : 0.0f;
            e[c] = t;
            lsum += t;
        }
    }
#pragma unroll
    for (int o = 16; o > 0; o >>= 1)
        lsum += __shfl_xor_sync(0xFFFFFFFF, lsum, o);
    __syncthreads();              // protect sred reuse
    if (lane == 0) sred[wid] = lsum;
    __syncthreads();
    float tot = sred[0];
#pragma unroll
    for (int w = 1; w < 16; w++) tot += sred[w];
    const float inv = 1.0f / tot;

    float4 y = make_float4(0.f, 0.f, 0.f, 0.f);
    if (j0 < valid) {
        y.x = x.x * inv; y.y = x.y * inv; y.z = x.z * inv; y.w = x.w * inv;
    }
    *(float4*)(row + j0) = y;
    if (j0 < bound) {
        rowh2[tid * 2]     = __floats2half2_rn(y.x, y.y);
        rowh2[tid * 2 + 1] = __floats2half2_rn(y.z, y.w);
    }
}

// ---------------------------------------------------------------------------
// Kernel 4: output = attn_h @ vp (NN GEMM via trans-ldmatrix B), fp32 out.
// K truncated at m0+128 (causal zeros beyond).
// ---------------------------------------------------------------------------
__global__ __launch_bounds__(NT, 4) void av_hmma(float* __restrict__ out) {
    extern __shared__ char sm[];
    const int m0 = blockIdx.x * 128, n0 = blockIdx.y * 64;
    const int b = blockIdx.z;
    const __half* A = g_attn_h + (size_t)b * Ss * Ss;
    const __half* B = g_vp + (size_t)b * Ss * Dd + n0;  // [t][d], col offset n0
    float* C = out + (size_t)b * Ss * Dd;

    ZERO_ACC(acc);
    gemm_main<Ss, Dd, true>(A + (size_t)m0 * Ss, B, (m0 + 128) / 64, sm, acc);

    const int lane = threadIdx.x & 31, warp = threadIdx.x >> 5;
    const int wm = warp & 1, wn = warp >> 1, g = lane >> 2, tk = lane & 3;
#pragma unroll
    for (int mi = 0; mi < 4; mi++) {
        const int r0 = m0 + wm * 64 + mi * 16 + g;
#pragma unroll
        for (int ni = 0; ni < 4; ni++) {
            const int col = n0 + wn * 32 + ni * 8 + tk * 2;
            *(float2*)&C[(size_t)r0 * Dd + col] =
                make_float2(acc[mi][ni][0], acc[mi][ni][1]);
            *(float2*)&C[(size_t)(r0 + 8) * Dd + col] =
                make_float2(acc[mi][ni][2], acc[mi][ni][3]);
        }
    }
}

// ---------------------------------------------------------------------------
// Host launch. d_out = [output (B*S*D) | attn (B*S*S)] fp32.
// ---------------------------------------------------------------------------
extern "C" void kernel_launch(void* const* d_in, const int* in_sizes, int n_in,
                              void* d_out, int out_size)
{
    const float* q  = (const float*)d_in[0];
    const float* k  = (const float*)d_in[1];
    const float* v  = (const float*)d_in[2];
    const float* Wq = (const float*)d_in[3];
    const float* bq = (const float*)d_in[4];
    const float* Wk = (const float*)d_in[5];
    const float* bk = (const float*)d_in[6];
    const float* Wv = (const float*)d_in[7];
    const float* bv = (const float*)d_in[8];

    float* out  = (float*)d_out;
    float* outO = out;                         // [B,S,D]
    float* attn = out + (size_t)Bb * Ss * Dd;  // [B,S,S]

    cudaFuncSetAttribute(proj_hmma, cudaFuncAttributeMaxDynamicSharedMemorySize, SMEMSZ);
    cudaFuncSetAttribute(scores_hmma, cudaFuncAttributeMaxDynamicSharedMemorySize, SMEMSZ);
    cudaFuncSetAttribute(av_hmma, cudaFuncAttributeMaxDynamicSharedMemorySize, SMEMSZ);

    // 0) fp32 -> fp16 conversions
    convert_kernel<<<dim3(4096, 1, 6), 512>>>(q, k, v, Wq, Wk, Wv);

    // 1) QKV projections
    proj_hmma<<<dim3(MT / 128, Dd / 64, 3), NT, SMEMSZ>>>(bq, bk, bv);

    // 2) causal raw scores
    scores_hmma<<<dim3(Ss / 128, Ss / 64, Bb), NT, SMEMSZ>>>(attn);

    // 3) softmax (fp32 in-place + fp16 copy, bounded)
    softmax_kernel<<<MT, 512>>>(attn);

    // 4) output = attn @ vp (NN, trans-ldmatrix B)
    av_hmma<<<dim3(Ss / 128, Dd / 64, Bb), NT, SMEMSZ>>>(outO);
}

// round 14
// speedup vs baseline: 1.0368x; 1.0368x over previous
#include <cuda_runtime.h>
#include <cuda_fp16.h>
#include <stdint.h>

// Problem constants
static constexpr int Bb = 8;
static constexpr int Ss = 2048;
static constexpr int Dd = 1024;
static constexpr int MT = Bb * Ss;
static constexpr float INV_TEMP = 1.0f / 32.0f;

// GEMM tiling: 128(M) x 64(N) x 64(K) stages, 2-stage cp.async pipeline.
// 128 threads / 4 warps per CTA, warp tile 64x32, 4 CTAs per SM (RF cap).
#define STAGE_SZ 24576           // A tile 16KB + B tile 8KB
#define SMEMSZ   49152           // 2 stages
#define NT 128

// fp16 scratch (device globals: allocation-free)
__device__ __half g_qx[(size_t)MT * Dd];
__device__ __half g_kx[(size_t)MT * Dd];
__device__ __half g_vx[(size_t)MT * Dd];
__device__ __half g_wq[(size_t)Dd * Dd];
__device__ __half g_wk[(size_t)Dd * Dd];
__device__ __half g_wv[(size_t)Dd * Dd];
__device__ __half g_qp[(size_t)MT * Dd];
__device__ __half g_kp[(size_t)MT * Dd];
__device__ __half g_vp[(size_t)MT * Dd];
__device__ __half g_attn_h[(size_t)Bb * Ss * Ss];  // fp16 softmax output

// ---------------------------------------------------------------------------
// PTX helpers
// ---------------------------------------------------------------------------
__device__ __forceinline__ uint32_t smem_u32(const void* p) {
    return (uint32_t)__cvta_generic_to_shared(p);
}
__device__ __forceinline__ uint32_t swz(uint32_t off) {
    return off ^ ((off >> 3) & 0x70);   // SW128 for 128B rows
}
__device__ __forceinline__ void cp16(uint32_t dst, const void* src) {
    asm volatile("cp.async.cg.shared.global [%0], [%1], 16;" :: "r"(dst), "l"(src));
}
__device__ __forceinline__ void ldsm4(uint32_t& r0, uint32_t& r1,
                                      uint32_t& r2, uint32_t& r3, uint32_t addr) {
    asm volatile("ldmatrix.sync.aligned.m8n8.x4.shared.b16 {%0,%1,%2,%3}, [%4];"
                 : "=r"(r0), "=r"(r1), "=r"(r2), "=r"(r3) : "r"(addr));
}
__device__ __forceinline__ void ldsm4t(uint32_t& r0, uint32_t& r1,
                                       uint32_t& r2, uint32_t& r3, uint32_t addr) {
    asm volatile("ldmatrix.sync.aligned.m8n8.x4.trans.shared.b16 {%0,%1,%2,%3}, [%4];"
                 : "=r"(r0), "=r"(r1), "=r"(r2), "=r"(r3) : "r"(addr));
}
__device__ __forceinline__ void mma16816(float c[4], const uint32_t a[4],
                                         const uint32_t b[2]) {
    asm volatile(
        "mma.sync.aligned.m16n8k16.row.col.f32.f16.f16.f32 "
        "{%0,%1,%2,%3}, {%4,%5,%6,%7}, {%8,%9}, {%0,%1,%2,%3};"
        : "+f"(c[0]), "+f"(c[1]), "+f"(c[2]), "+f"(c[3])
        : "r"(a[0]), "r"(a[1]), "r"(a[2]), "r"(a[3]), "r"(b[0]), "r"(b[1]));
}

// ---------------------------------------------------------------------------
// Stage loader. A: 128 rows x 64 k-cols (row-major, advance cols by kt).
// B (NT):     64 n-rows x 64 k-cols (row-major [n][k], advance cols by kt).
// B (TRANS):  64 k-rows x 64 n-cols (row-major [k][n], advance ROWS by kt).
// ---------------------------------------------------------------------------
template <int LDA, int LDB, bool BTRANS>
__device__ __forceinline__ void issue_stage(
    const __half* __restrict__ A, const __half* __restrict__ B, int kt,
    uint32_t abase, uint32_t bbase, int tid)
{
#pragma unroll
    for (int i = 0; i < 8; i++) {
        const int id = tid + i * NT;
        const int row = id >> 3, cc = id & 7;
        cp16(abase + swz(row * 128 + cc * 16), A + (size_t)row * LDA + kt + cc * 8);
    }
#pragma unroll
    for (int i = 0; i < 4; i++) {
        const int id = tid + i * NT;
        const int row = id >> 3, cc = id & 7;
        const __half* src = BTRANS
            ? B + (size_t)(kt + row) * LDB + cc * 8
            : B + (size_t)row * LDB + kt + cc * 8;
        cp16(bbase + swz(row * 128 + cc * 16), src);
    }
    asm volatile("cp.async.commit_group;");
}

// ---------------------------------------------------------------------------
// Compute one 128x64x64 stage. Warp grid 2(m) x 2(n); warp tile 64x32.
// ---------------------------------------------------------------------------
template <bool BTRANS>
__device__ __forceinline__ void compute_stage(
    uint32_t abase, uint32_t bbase, int wm, int wn, int lane,
    float acc[4][4][4])
{
    const int a_row = wm * 64 + (lane & 15);
    const int a_col = (lane >> 4) * 8;
    // NT path lane mapping
    const int b_row = wn * 32 + ((lane >> 4) * 8) + (lane & 7);
    const int b_col = ((lane >> 3) & 1) * 8;
    // TRANS path lane mapping: row = k (lane&15), col-block = (lane>>4)*8
    const int bt_k = lane & 15;
    const int bt_n = wn * 32 + (lane >> 4) * 8;
#pragma unroll
    for (int ks = 0; ks < 4; ks++) {
        uint32_t af[4][4], bf[4][2];
#pragma unroll
        for (int mi = 0; mi < 4; mi++)
            ldsm4(af[mi][0], af[mi][1], af[mi][2], af[mi][3],
                  abase + swz(((a_row + mi * 16) << 7) + (ks * 16 + a_col) * 2));
#pragma unroll
        for (int nj = 0; nj < 2; nj++) {
            if (BTRANS) {
                ldsm4t(bf[2 * nj][0], bf[2 * nj][1],
                       bf[2 * nj + 1][0], bf[2 * nj + 1][1],
                       bbase + swz(((ks * 16 + bt_k) << 7) + (bt_n + nj * 16) * 2));
            } else {
                ldsm4(bf[2 * nj][0], bf[2 * nj][1],
                      bf[2 * nj + 1][0], bf[2 * nj + 1][1],
                      bbase + swz(((b_row + nj * 16) << 7) + (ks * 16 + b_col) * 2));
            }
        }
#pragma unroll
        for (int mi = 0; mi < 4; mi++)
#pragma unroll
            for (int ni = 0; ni < 4; ni++)
                mma16816(acc[mi][ni], af[mi], bf[ni]);
    }
}

// ---------------------------------------------------------------------------
// Full GEMM mainloop. 2-stage pipeline.
// ---------------------------------------------------------------------------
template <int LDA, int LDB, bool BTRANS>
__device__ __forceinline__ void gemm_main(
    const __half* __restrict__ A, const __half* __restrict__ B,
    int nk, char* sm, float acc[4][4][4])
{
    const uint32_t smb = smem_u32(sm);
    const int tid = threadIdx.x, lane = tid & 31, warp = tid >> 5;
    const int wm = warp & 1, wn = warp >> 1;

    issue_stage<LDA, LDB, BTRANS>(A, B, 0, smb, smb + 16384, tid);

    for (int s = 0; s < nk; s++) {
        if (s + 1 < nk) {
            const uint32_t bn = smb + (uint32_t)((s + 1) & 1) * STAGE_SZ;
            issue_stage<LDA, LDB, BTRANS>(A, B, (s + 1) * 64, bn, bn + 16384, tid);
            asm volatile("cp.async.wait_group 1;");
        } else {
            asm volatile("cp.async.wait_group 0;");
        }
        __syncthreads();   // stage s visible
        const uint32_t bc = smb + (uint32_t)(s & 1) * STAGE_SZ;
        compute_stage<BTRANS>(bc, bc + 16384, wm, wn, lane, acc);
        __syncthreads();   // all warps done with buffer s&1 before refill
    }
}

#define ZERO_ACC(acc)                             \
    float acc[4][4][4];                           \
    _Pragma("unroll") for (int i = 0; i < 4; i++) \
    _Pragma("unroll") for (int j = 0; j < 4; j++) \
    _Pragma("unroll") for (int c = 0; c < 4; c++) acc[i][j][c] = 0.0f;

// ---------------------------------------------------------------------------
// Kernel 0: fp32 -> fp16 conversions (q,k,v,Wq,Wk,Wv)
// ---------------------------------------------------------------------------
__global__ __launch_bounds__(512) void convert_kernel(
    const float* __restrict__ q, const float* __restrict__ k,
    const float* __restrict__ v, const float* __restrict__ Wq,
    const float* __restrict__ Wk, const float* __restrict__ Wv)
{
    const int z = blockIdx.z;
    const float* src;
    __half* dst;
    size_t n8;
    if (z == 0)      { src = q;  dst = g_qx; n8 = (size_t)MT * Dd / 8; }
    else if (z == 1) { src = k;  dst = g_kx; n8 = (size_t)MT * Dd / 8; }
    else if (z == 2) { src = v;  dst = g_vx; n8 = (size_t)MT * Dd / 8; }
    else if (z == 3) { src = Wq; dst = g_wq; n8 = (size_t)Dd * Dd / 8; }
    else if (z == 4) { src = Wk; dst = g_wk; n8 = (size_t)Dd * Dd / 8; }
    else             { src = Wv; dst = g_wv; n8 = (size_t)Dd * Dd / 8; }
    const size_t i = (size_t)blockIdx.x * 512 + threadIdx.x;
    if (i >= n8) return;
    const float4* s4 = (const float4*)src;
    float4 a = s4[i * 2], b = s4[i * 2 + 1];
    __half2 h[4];
    h[0] = __floats2half2_rn(a.x, a.y);
    h[1] = __floats2half2_rn(a.z, a.w);
    h[2] = __floats2half2_rn(b.x, b.y);
    h[3] = __floats2half2_rn(b.z, b.w);
    ((uint4*)dst)[i] = *(uint4*)h;
}

// ---------------------------------------------------------------------------
// Kernel 1: QKV projections. z selects GEMM. Output fp16 (+bias).
// ---------------------------------------------------------------------------
__global__ __launch_bounds__(NT, 4) void proj_hmma(
    const float* __restrict__ bq, const float* __restrict__ bk,
    const float* __restrict__ bv)
{
    extern __shared__ char sm[];
    const int m0 = blockIdx.x * 128, n0 = blockIdx.y * 64, z = blockIdx.z;
    const __half *X, *W;
    const float* bias;
    __half* C;
    if (z == 0)      { X = g_qx; W = g_wq; bias = bq; C = g_qp; }
    else if (z == 1) { X = g_kx; W = g_wk; bias = bk; C = g_kp; }
    else             { X = g_vx; W = g_wv; bias = bv; C = g_vp; }

    ZERO_ACC(acc);
    gemm_main<Dd, Dd, false>(X + (size_t)m0 * Dd, W + (size_t)n0 * Dd, Dd / 64, sm, acc);

    const int lane = threadIdx.x & 31, warp = threadIdx.x >> 5;
    const int wm = warp & 1, wn = warp >> 1, g = lane >> 2, tk = lane & 3;
#pragma unroll
    for (int mi = 0; mi < 4; mi++) {
        const int r0 = m0 + wm * 64 + mi * 16 + g;
#pragma unroll
        for (int ni = 0; ni < 4; ni++) {
            const int col = n0 + wn * 32 + ni * 8 + tk * 2;
            const float bx = bias[col], by = bias[col + 1];
            *(__half2*)&C[(size_t)r0 * Dd + col] =
                __floats2half2_rn(acc[mi][ni][0] + bx, acc[mi][ni][1] + by);
            *(__half2*)&C[(size_t)(r0 + 8) * Dd + col] =
                __floats2half2_rn(acc[mi][ni][2] + bx, acc[mi][ni][3] + by);
        }
    }
}

// ---------------------------------------------------------------------------
// Kernel 2: causal raw scores, fp32 logits out (/32)
// ---------------------------------------------------------------------------
__global__ __launch_bounds__(NT, 4) void scores_hmma(float* __restrict__ attn) {
    const int m0 = blockIdx.x * 128, n0 = blockIdx.y * 64;
    if (n0 > m0 + 127) return;  // tile entirely above diagonal
    extern __shared__ char sm[];
    const int b = blockIdx.z;
    const __half* A = g_qp + (size_t)b * Ss * Dd;
    const __half* B = g_kp + (size_t)b * Ss * Dd;
    float* C = attn + (size_t)b * Ss * Ss;

    ZERO_ACC(acc);
    gemm_main<Dd, Dd, false>(A + (size_t)m0 * Dd, B + (size_t)n0 * Dd, Dd / 64, sm, acc);

    const int lane = threadIdx.x & 31, warp = threadIdx.x >> 5;
    const int wm = warp & 1, wn = warp >> 1, g = lane >> 2, tk = lane & 3;
#pragma unroll
    for (int mi = 0; mi < 4; mi++) {
        const int r0 = m0 + wm * 64 + mi * 16 + g;
#pragma unroll
        for (int ni = 0; ni < 4; ni++) {
            const int col = n0 + wn * 32 + ni * 8 + tk * 2;
            *(float2*)&C[(size_t)r0 * Ss + col] =
                make_float2(acc[mi][ni][0] * INV_TEMP, acc[mi][ni][1] * INV_TEMP);
            *(float2*)&C[(size_t)(r0 + 8) * Ss + col] =
                make_float2(acc[mi][ni][2] * INV_TEMP, acc[mi][ni][3] * INV_TEMP);
        }
    }
}

// ---------------------------------------------------------------------------
// Kernel 3: causal row softmax (fp32 in-place + fp16 copy).
// 256 threads, two float4 per thread; warp-shuffle reductions; __expf.
// ---------------------------------------------------------------------------
__global__ __launch_bounds__(256) void softmax_kernel(float* __restrict__ attn) {
    const int rix = blockIdx.x;
    const int b = rix / Ss;
    const int i = rix % Ss;
    float* row = attn + (size_t)b * Ss * Ss + (size_t)i * Ss;
    __half2* rowh2 = (__half2*)(g_attn_h + (size_t)b * Ss * Ss + (size_t)i * Ss);
    const int tid = threadIdx.x;
    const int lane = tid & 31, wid = tid >> 5;
    const int valid = i + 1;
    const int bound = ((i >> 7) + 1) << 7;   // 128-aligned causal bound

    float4 x[2];
    float lmax = -3.0e38f;
#pragma unroll
    for (int it = 0; it < 2; it++) {
        const int j0 = (tid + it * 256) * 4;
        if (j0 < valid) {
            x[it] = *(const float4*)(row + j0);
            float* e = (float*)&x[it];
#pragma unroll
            for (int c = 0; c < 4; c++)
                if (j0 + c < valid) lmax = fmaxf(lmax, e[c]);
        } else {
            x[it] = make_float4(0.f, 0.f, 0.f, 0.f);
        }
    }

    __shared__ float sred[8];
#pragma unroll
    for (int o = 16; o > 0; o >>= 1)
        lmax = fmaxf(lmax, __shfl_xor_sync(0xFFFFFFFF, lmax, o));
    if (lane == 0) sred[wid] = lmax;
    __syncthreads();
    float mx = sred[0];
#pragma unroll
    for (int w = 1; w < 8; w++) mx = fmaxf(mx, sred[w]);

    float lsum = 0.0f;
#pragma unroll
    for (int it = 0; it < 2; it++) {
        const int j0 = (tid + it * 256) * 4;
        float* e = (float*)&x[it];
        if (j0 < valid) {
#pragma unroll
            for (int c = 0; c < 4; c++) {
                const float t = (j0 + c < valid) ? __expf(e[c] - mx) : 0.0f;
                e[c] = t;
                lsum += t;
            }
        }
    }
#pragma unroll
    for (int o = 16; o > 0; o >>= 1)
        lsum += __shfl_xor_sync(0xFFFFFFFF, lsum, o);
    __syncthreads();              // protect sred reuse
    if (lane == 0) sred[wid] = lsum;
    __syncthreads();
    float tot = sred[0];
#pragma unroll
    for (int w = 1; w < 8; w++) tot += sred[w];
    const float inv = 1.0f / tot;

#pragma unroll
    for (int it = 0; it < 2; it++) {
        const int j4 = tid + it * 256;
        const int j0 = j4 * 4;
        float* e = (float*)&x[it];
        float4 y;
        if (j0 < valid) {
            y.x = e[0] * inv; y.y = e[1] * inv; y.z = e[2] * inv; y.w = e[3] * inv;
        } else {
            y = make_float4(0.f, 0.f, 0.f, 0.f);
        }
        *(float4*)(row + j0) = y;
        if (j0 < bound) {
            rowh2[j4 * 2]     = __floats2half2_rn(y.x, y.y);
            rowh2[j4 * 2 + 1] = __floats2half2_rn(y.z, y.w);
        }
    }
}

// ---------------------------------------------------------------------------
// Kernel 4: output = attn_h @ vp (NN GEMM via trans-ldmatrix B), fp32 out.
// K truncated at m0+128. Heaviest panels (large m0) scheduled FIRST (LPT).
// ---------------------------------------------------------------------------
__global__ __launch_bounds__(NT, 4) void av_hmma(float* __restrict__ out) {
    extern __shared__ char sm[];
    const int m0 = (Ss / 128 - 1 - (int)blockIdx.x) * 128;   // descending work
    const int n0 = blockIdx.y * 64;
    const int b = blockIdx.z;
    const __half* A = g_attn_h + (size_t)b * Ss * Ss;
    const __half* B = g_vp + (size_t)b * Ss * Dd + n0;  // [t][d], col offset n0
    float* C = out + (size_t)b * Ss * Dd;

    ZERO_ACC(acc);
    gemm_main<Ss, Dd, true>(A + (size_t)m0 * Ss, B, (m0 + 128) / 64, sm, acc);

    const int lane = threadIdx.x & 31, warp = threadIdx.x >> 5;
    const int wm = warp & 1, wn = warp >> 1, g = lane >> 2, tk = lane & 3;
#pragma unroll
    for (int mi = 0; mi < 4; mi++) {
        const int r0 = m0 + wm * 64 + mi * 16 + g;
#pragma unroll
        for (int ni = 0; ni < 4; ni++) {
            const int col = n0 + wn * 32 + ni * 8 + tk * 2;
            *(float2*)&C[(size_t)r0 * Dd + col] =
                make_float2(acc[mi][ni][0], acc[mi][ni][1]);
            *(float2*)&C[(size_t)(r0 + 8) * Dd + col] =
                make_float2(acc[mi][ni][2], acc[mi][ni][3]);
        }
    }
}

// ---------------------------------------------------------------------------
// Host launch. d_out = [output (B*S*D) | attn (B*S*S)] fp32.
// ---------------------------------------------------------------------------
extern "C" void kernel_launch(void* const* d_in, const int* in_sizes, int n_in,
                              void* d_out, int out_size)
{
    const float* q  = (const float*)d_in[0];
    const float* k  = (const float*)d_in[1];
    const float* v  = (const float*)d_in[2];
    const float* Wq = (const float*)d_in[3];
    const float* bq = (const float*)d_in[4];
    const float* Wk = (const float*)d_in[5];
    const float* bk = (const float*)d_in[6];
    const float* Wv = (const float*)d_in[7];
    const float* bv = (const float*)d_in[8];

    float* out  = (float*)d_out;
    float* outO = out;                         // [B,S,D]
    float* attn = out + (size_t)Bb * Ss * Dd;  // [B,S,S]

    cudaFuncSetAttribute(proj_hmma, cudaFuncAttributeMaxDynamicSharedMemorySize, SMEMSZ);
    cudaFuncSetAttribute(scores_hmma, cudaFuncAttributeMaxDynamicSharedMemorySize, SMEMSZ);
    cudaFuncSetAttribute(av_hmma, cudaFuncAttributeMaxDynamicSharedMemorySize, SMEMSZ);

    // 0) fp32 -> fp16 conversions
    convert_kernel<<<dim3(4096, 1, 6), 512>>>(q, k, v, Wq, Wk, Wv);

    // 1) QKV projections
    proj_hmma<<<dim3(MT / 128, Dd / 64, 3), NT, SMEMSZ>>>(bq, bk, bv);

    // 2) causal raw scores
    scores_hmma<<<dim3(Ss / 128, Ss / 64, Bb), NT, SMEMSZ>>>(attn);

    // 3) softmax (fp32 in-place + fp16 copy, bounded)
    softmax_kernel<<<MT, 256>>>(attn);

    // 4) output = attn @ vp (NN, trans-ldmatrix B; heavy panels first)
    av_hmma<<<dim3(Ss / 128, Dd / 64, Bb), NT, SMEMSZ>>>(outO);
}

// round 15
// speedup vs baseline: 1.0378x; 1.0010x over previous
#include <cuda_runtime.h>
#include <cuda_fp16.h>
#include <stdint.h>

// Problem constants
static constexpr int Bb = 8;
static constexpr int Ss = 2048;
static constexpr int Dd = 1024;
static constexpr int MT = Bb * Ss;
static constexpr float INV_TEMP = 1.0f / 32.0f;

// GEMM tiling: 128(M) x 64(N) x 64(K) stages, 2-stage cp.async pipeline.
// 128 threads / 4 warps per CTA, warp tile 64x32, 4 CTAs per SM (RF cap).
#define STAGE_SZ 24576           // A tile 16KB + B tile 8KB
#define SMEMSZ   49152           // 2 stages
#define NT 128

// fp16 scratch (device globals: allocation-free)
__device__ __half g_qx[(size_t)MT * Dd];
__device__ __half g_kx[(size_t)MT * Dd];
__device__ __half g_vx[(size_t)MT * Dd];
__device__ __half g_wq[(size_t)Dd * Dd];
__device__ __half g_wk[(size_t)Dd * Dd];
__device__ __half g_wv[(size_t)Dd * Dd];
__device__ __half g_qp[(size_t)MT * Dd];
__device__ __half g_kp[(size_t)MT * Dd];
__device__ __half g_vp[(size_t)MT * Dd];
__device__ __half g_attn_h[(size_t)Bb * Ss * Ss];  // fp16 softmax output

// ---------------------------------------------------------------------------
// PTX helpers
// ---------------------------------------------------------------------------
__device__ __forceinline__ uint32_t smem_u32(const void* p) {
    return (uint32_t)__cvta_generic_to_shared(p);
}
__device__ __forceinline__ uint32_t swz(uint32_t off) {
    return off ^ ((off >> 3) & 0x70);   // SW128 for 128B rows
}
__device__ __forceinline__ void cp16(uint32_t dst, const void* src) {
    asm volatile("cp.async.cg.shared.global [%0], [%1], 16;" :: "r"(dst), "l"(src));
}
__device__ __forceinline__ void ldsm4(uint32_t& r0, uint32_t& r1,
                                      uint32_t& r2, uint32_t& r3, uint32_t addr) {
    asm volatile("ldmatrix.sync.aligned.m8n8.x4.shared.b16 {%0,%1,%2,%3}, [%4];"
                 : "=r"(r0), "=r"(r1), "=r"(r2), "=r"(r3) : "r"(addr));
}
__device__ __forceinline__ void ldsm4t(uint32_t& r0, uint32_t& r1,
                                       uint32_t& r2, uint32_t& r3, uint32_t addr) {
    asm volatile("ldmatrix.sync.aligned.m8n8.x4.trans.shared.b16 {%0,%1,%2,%3}, [%4];"
                 : "=r"(r0), "=r"(r1), "=r"(r2), "=r"(r3) : "r"(addr));
}
__device__ __forceinline__ void mma16816(float c[4], const uint32_t a[4],
                                         const uint32_t b[2]) {
    asm volatile(
        "mma.sync.aligned.m16n8k16.row.col.f32.f16.f16.f32 "
        "{%0,%1,%2,%3}, {%4,%5,%6,%7}, {%8,%9}, {%0,%1,%2,%3};"
        : "+f"(c[0]), "+f"(c[1]), "+f"(c[2]), "+f"(c[3])
        : "r"(a[0]), "r"(a[1]), "r"(a[2]), "r"(a[3]), "r"(b[0]), "r"(b[1]));
}

// ---------------------------------------------------------------------------
// Stage loader. A: 128 rows x 64 k-cols (row-major, advance cols by kt).
// B (NT):     64 n-rows x 64 k-cols (row-major [n][k], advance cols by kt).
// B (TRANS):  64 k-rows x 64 n-cols (row-major [k][n], advance ROWS by kt).
// ---------------------------------------------------------------------------
template <int LDA, int LDB, bool BTRANS>
__device__ __forceinline__ void issue_stage(
    const __half* __restrict__ A, const __half* __restrict__ B, int kt,
    uint32_t abase, uint32_t bbase, int tid)
{
#pragma unroll
    for (int i = 0; i < 8; i++) {
        const int id = tid + i * NT;
        const int row = id >> 3, cc = id & 7;
        cp16(abase + swz(row * 128 + cc * 16), A + (size_t)row * LDA + kt + cc * 8);
    }
#pragma unroll
    for (int i = 0; i < 4; i++) {
        const int id = tid + i * NT;
        const int row = id >> 3, cc = id & 7;
        const __half* src = BTRANS
            ? B + (size_t)(kt + row) * LDB + cc * 8
            : B + (size_t)row * LDB + kt + cc * 8;
        cp16(bbase + swz(row * 128 + cc * 16), src);
    }
    asm volatile("cp.async.commit_group;");
}

// ---------------------------------------------------------------------------
// Compute one 128x64x64 stage. Warp grid 2(m) x 2(n); warp tile 64x32.
// ---------------------------------------------------------------------------
template <bool BTRANS>
__device__ __forceinline__ void compute_stage(
    uint32_t abase, uint32_t bbase, int wm, int wn, int lane,
    float acc[4][4][4])
{
    const int a_row = wm * 64 + (lane & 15);
    const int a_col = (lane >> 4) * 8;
    // NT path lane mapping
    const int b_row = wn * 32 + ((lane >> 4) * 8) + (lane & 7);
    const int b_col = ((lane >> 3) & 1) * 8;
    // TRANS path lane mapping: row = k (lane&15), col-block = (lane>>4)*8
    const int bt_k = lane & 15;
    const int bt_n = wn * 32 + (lane >> 4) * 8;
#pragma unroll
    for (int ks = 0; ks < 4; ks++) {
        uint32_t af[4][4], bf[4][2];
#pragma unroll
        for (int mi = 0; mi < 4; mi++)
            ldsm4(af[mi][0], af[mi][1], af[mi][2], af[mi][3],
                  abase + swz(((a_row + mi * 16) << 7) + (ks * 16 + a_col) * 2));
#pragma unroll
        for (int nj = 0; nj < 2; nj++) {
            if (BTRANS) {
                ldsm4t(bf[2 * nj][0], bf[2 * nj][1],
                       bf[2 * nj + 1][0], bf[2 * nj + 1][1],
                       bbase + swz(((ks * 16 + bt_k) << 7) + (bt_n + nj * 16) * 2));
            } else {
                ldsm4(bf[2 * nj][0], bf[2 * nj][1],
                      bf[2 * nj + 1][0], bf[2 * nj + 1][1],
                      bbase + swz(((b_row + nj * 16) << 7) + (ks * 16 + b_col) * 2));
            }
        }
#pragma unroll
        for (int mi = 0; mi < 4; mi++)
#pragma unroll
            for (int ni = 0; ni < 4; ni++)
                mma16816(acc[mi][ni], af[mi], bf[ni]);
    }
}

// ---------------------------------------------------------------------------
// Full GEMM mainloop. 2-stage pipeline.
// ---------------------------------------------------------------------------
template <int LDA, int LDB, bool BTRANS>
__device__ __forceinline__ void gemm_main(
    const __half* __restrict__ A, const __half* __restrict__ B,
    int nk, char* sm, float acc[4][4][4])
{
    const uint32_t smb = smem_u32(sm);
    const int tid = threadIdx.x, lane = tid & 31, warp = tid >> 5;
    const int wm = warp & 1, wn = warp >> 1;

    issue_stage<LDA, LDB, BTRANS>(A, B, 0, smb, smb + 16384, tid);

    for (int s = 0; s < nk; s++) {
        if (s + 1 < nk) {
            const uint32_t bn = smb + (uint32_t)((s + 1) & 1) * STAGE_SZ;
            issue_stage<LDA, LDB, BTRANS>(A, B, (s + 1) * 64, bn, bn + 16384, tid);
            asm volatile("cp.async.wait_group 1;");
        } else {
            asm volatile("cp.async.wait_group 0;");
        }
        __syncthreads();   // stage s visible
        const uint32_t bc = smb + (uint32_t)(s & 1) * STAGE_SZ;
        compute_stage<BTRANS>(bc, bc + 16384, wm, wn, lane, acc);
        __syncthreads();   // all warps done with buffer s&1 before refill
    }
}

#define ZERO_ACC(acc)                             \
    float acc[4][4][4];                           \
    _Pragma("unroll") for (int i = 0; i < 4; i++) \
    _Pragma("unroll") for (int j = 0; j < 4; j++) \
    _Pragma("unroll") for (int c = 0; c < 4; c++) acc[i][j][c] = 0.0f;

// ---------------------------------------------------------------------------
// Kernel 0: fp32 -> fp16 conversions (q,k,v,Wq,Wk,Wv)
// ---------------------------------------------------------------------------
__global__ __launch_bounds__(512) void convert_kernel(
    const float* __restrict__ q, const float* __restrict__ k,
    const float* __restrict__ v, const float* __restrict__ Wq,
    const float* __restrict__ Wk, const float* __restrict__ Wv)
{
    const int z = blockIdx.z;
    const float* src;
    __half* dst;
    size_t n8;
    if (z == 0)      { src = q;  dst = g_qx; n8 = (size_t)MT * Dd / 8; }
    else if (z == 1) { src = k;  dst = g_kx; n8 = (size_t)MT * Dd / 8; }
    else if (z == 2) { src = v;  dst = g_vx; n8 = (size_t)MT * Dd / 8; }
    else if (z == 3) { src = Wq; dst = g_wq; n8 = (size_t)Dd * Dd / 8; }
    else if (z == 4) { src = Wk; dst = g_wk; n8 = (size_t)Dd * Dd / 8; }
    else             { src = Wv; dst = g_wv; n8 = (size_t)Dd * Dd / 8; }
    const size_t i = (size_t)blockIdx.x * 512 + threadIdx.x;
    if (i >= n8) return;
    const float4* s4 = (const float4*)src;
    float4 a = s4[i * 2], b = s4[i * 2 + 1];
    __half2 h[4];
    h[0] = __floats2half2_rn(a.x, a.y);
    h[1] = __floats2half2_rn(a.z, a.w);
    h[2] = __floats2half2_rn(b.x, b.y);
    h[3] = __floats2half2_rn(b.z, b.w);
    ((uint4*)dst)[i] = *(uint4*)h;
}

// ---------------------------------------------------------------------------
// Kernel 1: QKV projections. z selects GEMM. Output fp16 (+bias).
// ---------------------------------------------------------------------------
__global__ __launch_bounds__(NT, 4) void proj_hmma(
    const float* __restrict__ bq, const float* __restrict__ bk,
    const float* __restrict__ bv)
{
    extern __shared__ char sm[];
    const int m0 = blockIdx.x * 128, n0 = blockIdx.y * 64, z = blockIdx.z;
    const __half *X, *W;
    const float* bias;
    __half* C;
    if (z == 0)      { X = g_qx; W = g_wq; bias = bq; C = g_qp; }
    else if (z == 1) { X = g_kx; W = g_wk; bias = bk; C = g_kp; }
    else             { X = g_vx; W = g_wv; bias = bv; C = g_vp; }

    ZERO_ACC(acc);
    gemm_main<Dd, Dd, false>(X + (size_t)m0 * Dd, W + (size_t)n0 * Dd, Dd / 64, sm, acc);

    const int lane = threadIdx.x & 31, warp = threadIdx.x >> 5;
    const int wm = warp & 1, wn = warp >> 1, g = lane >> 2, tk = lane & 3;
#pragma unroll
    for (int mi = 0; mi < 4; mi++) {
        const int r0 = m0 + wm * 64 + mi * 16 + g;
#pragma unroll
        for (int ni = 0; ni < 4; ni++) {
            const int col = n0 + wn * 32 + ni * 8 + tk * 2;
            const float bx = bias[col], by = bias[col + 1];
            *(__half2*)&C[(size_t)r0 * Dd + col] =
                __floats2half2_rn(acc[mi][ni][0] + bx, acc[mi][ni][1] + by);
            *(__half2*)&C[(size_t)(r0 + 8) * Dd + col] =
                __floats2half2_rn(acc[mi][ni][2] + bx, acc[mi][ni][3] + by);
        }
    }
}

// ---------------------------------------------------------------------------
// Kernel 2: causal raw scores, fp32 logits out (/32).
// Above-diagonal tiles write the final fp32 zeros (streaming stores that
// overlap with the live GEMM CTAs); softmax then never touches j >= bound.
// ---------------------------------------------------------------------------
__global__ __launch_bounds__(NT, 4) void scores_hmma(float* __restrict__ attn) {
    const int m0 = blockIdx.x * 128, n0 = blockIdx.y * 64;
    const int b = blockIdx.z;
    float* C = attn + (size_t)b * Ss * Ss;

    if (n0 > m0 + 127) {
        // final zeros for this entirely-above-diagonal tile
        const float4 z4 = make_float4(0.f, 0.f, 0.f, 0.f);
        const int tid = threadIdx.x;
#pragma unroll
        for (int i = 0; i < 16; i++) {
            const int id = tid + i * NT;           // 0..2047
            const int row = id >> 4, c4 = id & 15; // 128 rows x 16 float4
            *(float4*)&C[(size_t)(m0 + row) * Ss + n0 + c4 * 4] = z4;
        }
        return;
    }

    extern __shared__ char sm[];
    const __half* A = g_qp + (size_t)b * Ss * Dd;
    const __half* B = g_kp + (size_t)b * Ss * Dd;

    ZERO_ACC(acc);
    gemm_main<Dd, Dd, false>(A + (size_t)m0 * Dd, B + (size_t)n0 * Dd, Dd / 64, sm, acc);

    const int lane = threadIdx.x & 31, warp = threadIdx.x >> 5;
    const int wm = warp & 1, wn = warp >> 1, g = lane >> 2, tk = lane & 3;
#pragma unroll
    for (int mi = 0; mi < 4; mi++) {
        const int r0 = m0 + wm * 64 + mi * 16 + g;
#pragma unroll
        for (int ni = 0; ni < 4; ni++) {
            const int col = n0 + wn * 32 + ni * 8 + tk * 2;
            *(float2*)&C[(size_t)r0 * Ss + col] =
                make_float2(acc[mi][ni][0] * INV_TEMP, acc[mi][ni][1] * INV_TEMP);
            *(float2*)&C[(size_t)(r0 + 8) * Ss + col] =
                make_float2(acc[mi][ni][2] * INV_TEMP, acc[mi][ni][3] * INV_TEMP);
        }
    }
}

// ---------------------------------------------------------------------------
// Kernel 3: causal row softmax (fp32 in-place + fp16 copy).
// Touches only j < bound; zeros beyond were written by scores' dead tiles.
// 256 threads, two float4 per thread; warp-shuffle reductions; __expf.
// ---------------------------------------------------------------------------
__global__ __launch_bounds__(256) void softmax_kernel(float* __restrict__ attn) {
    const int rix = blockIdx.x;
    const int b = rix / Ss;
    const int i = rix % Ss;
    float* row = attn + (size_t)b * Ss * Ss + (size_t)i * Ss;
    __half2* rowh2 = (__half2*)(g_attn_h + (size_t)b * Ss * Ss + (size_t)i * Ss);
    const int tid = threadIdx.x;
    const int lane = tid & 31, wid = tid >> 5;
    const int valid = i + 1;
    const int bound = ((i >> 7) + 1) << 7;   // 128-aligned causal bound

    float4 x[2];
    float lmax = -3.0e38f;
#pragma unroll
    for (int it = 0; it < 2; it++) {
        const int j0 = (tid + it * 256) * 4;
        if (j0 < valid) {
            x[it] = *(const float4*)(row + j0);
            float* e = (float*)&x[it];
#pragma unroll
            for (int c = 0; c < 4; c++)
                if (j0 + c < valid) lmax = fmaxf(lmax, e[c]);
        } else {
            x[it] = make_float4(0.f, 0.f, 0.f, 0.f);
        }
    }

    __shared__ float sred[8];
#pragma unroll
    for (int o = 16; o > 0; o >>= 1)
        lmax = fmaxf(lmax, __shfl_xor_sync(0xFFFFFFFF, lmax, o));
    if (lane == 0) sred[wid] = lmax;
    __syncthreads();
    float mx = sred[0];
#pragma unroll
    for (int w = 1; w < 8; w++) mx = fmaxf(mx, sred[w]);

    float lsum = 0.0f;
#pragma unroll
    for (int it = 0; it < 2; it++) {
        const int j0 = (tid + it * 256) * 4;
        float* e = (float*)&x[it];
        if (j0 < valid) {
#pragma unroll
            for (int c = 0; c < 4; c++) {
                const float t = (j0 + c < valid) ? __expf(e[c] - mx) : 0.0f;
                e[c] = t;
                lsum += t;
            }
        }
    }
#pragma unroll
    for (int o = 16; o > 0; o >>= 1)
        lsum += __shfl_xor_sync(0xFFFFFFFF, lsum, o);
    __syncthreads();              // protect sred reuse
    if (lane == 0) sred[wid] = lsum;
    __syncthreads();
    float tot = sred[0];
#pragma unroll
    for (int w = 1; w < 8; w++) tot += sred[w];
    const float inv = 1.0f / tot;

#pragma unroll
    for (int it = 0; it < 2; it++) {
        const int j4 = tid + it * 256;
        const int j0 = j4 * 4;
        if (j0 >= bound) continue;   // beyond bound: zeros already in place
        float* e = (float*)&x[it];
        float4 y;
        if (j0 < valid) {
            y.x = e[0] * inv; y.y = e[1] * inv; y.z = e[2] * inv; y.w = e[3] * inv;
        } else {
            y = make_float4(0.f, 0.f, 0.f, 0.f);
        }
        *(float4*)(row + j0) = y;
        rowh2[j4 * 2]     = __floats2half2_rn(y.x, y.y);
        rowh2[j4 * 2 + 1] = __floats2half2_rn(y.z, y.w);
    }
}

// ---------------------------------------------------------------------------
// Kernel 4: output = attn_h @ vp (NN GEMM via trans-ldmatrix B), fp32 out.
// K truncated at m0+128. Heaviest panels (large m0) scheduled FIRST (LPT).
// ---------------------------------------------------------------------------
__global__ __launch_bounds__(NT, 4) void av_hmma(float* __restrict__ out) {
    extern __shared__ char sm[];
    const int m0 = (Ss / 128 - 1 - (int)blockIdx.x) * 128;   // descending work
    const int n0 = blockIdx.y * 64;
    const int b = blockIdx.z;
    const __half* A = g_attn_h + (size_t)b * Ss * Ss;
    const __half* B = g_vp + (size_t)b * Ss * Dd + n0;  // [t][d], col offset n0
    float* C = out + (size_t)b * Ss * Dd;

    ZERO_ACC(acc);
    gemm_main<Ss, Dd, true>(A + (size_t)m0 * Ss, B, (m0 + 128) / 64, sm, acc);

    const int lane = threadIdx.x & 31, warp = threadIdx.x >> 5;
    const int wm = warp & 1, wn = warp >> 1, g = lane >> 2, tk = lane & 3;
#pragma unroll
    for (int mi = 0; mi < 4; mi++) {
        const int r0 = m0 + wm * 64 + mi * 16 + g;
#pragma unroll
        for (int ni = 0; ni < 4; ni++) {
            const int col = n0 + wn * 32 + ni * 8 + tk * 2;
            *(float2*)&C[(size_t)r0 * Dd + col] =
                make_float2(acc[mi][ni][0], acc[mi][ni][1]);
            *(float2*)&C[(size_t)(r0 + 8) * Dd + col] =
                make_float2(acc[mi][ni][2], acc[mi][ni][3]);
        }
    }
}

// ---------------------------------------------------------------------------
// Host launch. d_out = [output (B*S*D) | attn (B*S*S)] fp32.
// ---------------------------------------------------------------------------
extern "C" void kernel_launch(void* const* d_in, const int* in_sizes, int n_in,
                              void* d_out, int out_size)
{
    const float* q  = (const float*)d_in[0];
    const float* k  = (const float*)d_in[1];
    const float* v  = (const float*)d_in[2];
    const float* Wq = (const float*)d_in[3];
    const float* bq = (const float*)d_in[4];
    const float* Wk = (const float*)d_in[5];
    const float* bk = (const float*)d_in[6];
    const float* Wv = (const float*)d_in[7];
    const float* bv = (const float*)d_in[8];

    float* out  = (float*)d_out;
    float* outO = out;                         // [B,S,D]
    float* attn = out + (size_t)Bb * Ss * Dd;  // [B,S,S]

    cudaFuncSetAttribute(proj_hmma, cudaFuncAttributeMaxDynamicSharedMemorySize, SMEMSZ);
    cudaFuncSetAttribute(scores_hmma, cudaFuncAttributeMaxDynamicSharedMemorySize, SMEMSZ);
    cudaFuncSetAttribute(av_hmma, cudaFuncAttributeMaxDynamicSharedMemorySize, SMEMSZ);

    // 0) fp32 -> fp16 conversions
    convert_kernel<<<dim3(4096, 1, 6), 512>>>(q, k, v, Wq, Wk, Wv);

    // 1) QKV projections
    proj_hmma<<<dim3(MT / 128, Dd / 64, 3), NT, SMEMSZ>>>(bq, bk, bv);

    // 2) causal raw scores (+ final zeros from above-diagonal tiles)
    scores_hmma<<<dim3(Ss / 128, Ss / 64, Bb), NT, SMEMSZ>>>(attn);

    // 3) softmax (fp32 in-place + fp16 copy, bounded)
    softmax_kernel<<<MT, 256>>>(attn);

    // 4) output = attn @ vp (NN, trans-ldmatrix B; heavy panels first)
    av_hmma<<<dim3(Ss / 128, Dd / 64, Bb), NT, SMEMSZ>>>(outO);
}

// round 16
// speedup vs baseline: 1.0395x; 1.0016x over previous
#include <cuda_runtime.h>
#include <cuda_fp16.h>
#include <stdint.h>

// Problem constants
static constexpr int Bb = 8;
static constexpr int Ss = 2048;
static constexpr int Dd = 1024;
static constexpr int MT = Bb * Ss;
static constexpr float INV_TEMP = 1.0f / 32.0f;

// GEMM tiling: 128(M) x 64(N) x 64(K) stages, 3-stage cp.async pipeline,
// ONE barrier per stage. 128 threads / 4 warps per CTA, warp tile 64x32,
// 3 CTAs per SM (216 KB smem).
#define STAGE_SZ 24576           // A tile 16KB + B tile 8KB
#define SMEMSZ   73728           // 3 stages
#define NT 128

// fp16 scratch (device globals: allocation-free)
__device__ __half g_qx[(size_t)MT * Dd];
__device__ __half g_kx[(size_t)MT * Dd];
__device__ __half g_vx[(size_t)MT * Dd];
__device__ __half g_wq[(size_t)Dd * Dd];
__device__ __half g_wk[(size_t)Dd * Dd];
__device__ __half g_wv[(size_t)Dd * Dd];
__device__ __half g_qp[(size_t)MT * Dd];
__device__ __half g_kp[(size_t)MT * Dd];
__device__ __half g_vp[(size_t)MT * Dd];
__device__ __half g_attn_h[(size_t)Bb * Ss * Ss];  // fp16 softmax output

// ---------------------------------------------------------------------------
// PTX helpers
// ---------------------------------------------------------------------------
__device__ __forceinline__ uint32_t smem_u32(const void* p) {
    return (uint32_t)__cvta_generic_to_shared(p);
}
__device__ __forceinline__ uint32_t swz(uint32_t off) {
    return off ^ ((off >> 3) & 0x70);   // SW128 for 128B rows
}
__device__ __forceinline__ void cp16(uint32_t dst, const void* src) {
    asm volatile("cp.async.cg.shared.global [%0], [%1], 16;" :: "r"(dst), "l"(src));
}
__device__ __forceinline__ void ldsm4(uint32_t& r0, uint32_t& r1,
                                      uint32_t& r2, uint32_t& r3, uint32_t addr) {
    asm volatile("ldmatrix.sync.aligned.m8n8.x4.shared.b16 {%0,%1,%2,%3}, [%4];"
                 : "=r"(r0), "=r"(r1), "=r"(r2), "=r"(r3) : "r"(addr));
}
__device__ __forceinline__ void ldsm4t(uint32_t& r0, uint32_t& r1,
                                       uint32_t& r2, uint32_t& r3, uint32_t addr) {
    asm volatile("ldmatrix.sync.aligned.m8n8.x4.trans.shared.b16 {%0,%1,%2,%3}, [%4];"
                 : "=r"(r0), "=r"(r1), "=r"(r2), "=r"(r3) : "r"(addr));
}
__device__ __forceinline__ void mma16816(float c[4], const uint32_t a[4],
                                         const uint32_t b[2]) {
    asm volatile(
        "mma.sync.aligned.m16n8k16.row.col.f32.f16.f16.f32 "
        "{%0,%1,%2,%3}, {%4,%5,%6,%7}, {%8,%9}, {%0,%1,%2,%3};"
        : "+f"(c[0]), "+f"(c[1]), "+f"(c[2]), "+f"(c[3])
        : "r"(a[0]), "r"(a[1]), "r"(a[2]), "r"(a[3]), "r"(b[0]), "r"(b[1]));
}

// ---------------------------------------------------------------------------
// Stage loader. A: 128 rows x 64 k-cols (row-major, advance cols by kt).
// B (NT):     64 n-rows x 64 k-cols (row-major [n][k], advance cols by kt).
// B (TRANS):  64 k-rows x 64 n-cols (row-major [k][n], advance ROWS by kt).
// ---------------------------------------------------------------------------
template <int LDA, int LDB, bool BTRANS>
__device__ __forceinline__ void issue_stage(
    const __half* __restrict__ A, const __half* __restrict__ B, int kt,
    uint32_t abase, uint32_t bbase, int tid)
{
#pragma unroll
    for (int i = 0; i < 8; i++) {
        const int id = tid + i * NT;
        const int row = id >> 3, cc = id & 7;
        cp16(abase + swz(row * 128 + cc * 16), A + (size_t)row * LDA + kt + cc * 8);
    }
#pragma unroll
    for (int i = 0; i < 4; i++) {
        const int id = tid + i * NT;
        const int row = id >> 3, cc = id & 7;
        const __half* src = BTRANS
            ? B + (size_t)(kt + row) * LDB + cc * 8
            : B + (size_t)row * LDB + kt + cc * 8;
        cp16(bbase + swz(row * 128 + cc * 16), src);
    }
    asm volatile("cp.async.commit_group;");
}

// ---------------------------------------------------------------------------
// Compute one 128x64x64 stage. Warp grid 2(m) x 2(n); warp tile 64x32.
// ---------------------------------------------------------------------------
template <bool BTRANS>
__device__ __forceinline__ void compute_stage(
    uint32_t abase, uint32_t bbase, int wm, int wn, int lane,
    float acc[4][4][4])
{
    const int a_row = wm * 64 + (lane & 15);
    const int a_col = (lane >> 4) * 8;
    // NT path lane mapping
    const int b_row = wn * 32 + ((lane >> 4) * 8) + (lane & 7);
    const int b_col = ((lane >> 3) & 1) * 8;
    // TRANS path lane mapping: row = k (lane&15), col-block = (lane>>4)*8
    const int bt_k = lane & 15;
    const int bt_n = wn * 32 + (lane >> 4) * 8;
#pragma unroll
    for (int ks = 0; ks < 4; ks++) {
        uint32_t af[4][4], bf[4][2];
#pragma unroll
        for (int mi = 0; mi < 4; mi++)
            ldsm4(af[mi][0], af[mi][1], af[mi][2], af[mi][3],
                  abase + swz(((a_row + mi * 16) << 7) + (ks * 16 + a_col) * 2));
#pragma unroll
        for (int nj = 0; nj < 2; nj++) {
            if (BTRANS) {
                ldsm4t(bf[2 * nj][0], bf[2 * nj][1],
                       bf[2 * nj + 1][0], bf[2 * nj + 1][1],
                       bbase + swz(((ks * 16 + bt_k) << 7) + (bt_n + nj * 16) * 2));
            } else {
                ldsm4(bf[2 * nj][0], bf[2 * nj][1],
                      bf[2 * nj + 1][0], bf[2 * nj + 1][1],
                      bbase + swz(((b_row + nj * 16) << 7) + (ks * 16 + b_col) * 2));
            }
        }
#pragma unroll
        for (int mi = 0; mi < 4; mi++)
#pragma unroll
            for (int ni = 0; ni < 4; ni++)
                mma16816(acc[mi][ni], af[mi], bf[ni]);
    }
}

// ---------------------------------------------------------------------------
// Full GEMM mainloop. 3-stage pipeline, ONE barrier per stage, 2 stages of
// loads in flight. The barrier before compute(s) also guarantees all warps
// finished compute(s-1), making buffer (s+2)%3 == (s-1)%3 safe to refill.
// ---------------------------------------------------------------------------
template <int LDA, int LDB, bool BTRANS>
__device__ __forceinline__ void gemm_main(
    const __half* __restrict__ A, const __half* __restrict__ B,
    int nk, char* sm, float acc[4][4][4])
{
    const uint32_t smb = smem_u32(sm);
    const int tid = threadIdx.x, lane = tid & 31, warp = tid >> 5;
    const int wm = warp & 1, wn = warp >> 1;

    issue_stage<LDA, LDB, BTRANS>(A, B, 0, smb, smb + 16384, tid);
    if (nk > 1) {
        const uint32_t b1 = smb + STAGE_SZ;
        issue_stage<LDA, LDB, BTRANS>(A, B, 64, b1, b1 + 16384, tid);
    }

    for (int s = 0; s < nk; s++) {
        if (s + 1 < nk) asm volatile("cp.async.wait_group 1;");
        else            asm volatile("cp.async.wait_group 0;");
        __syncthreads();   // stage s visible; all warps done with compute(s-1)
        if (s + 2 < nk) {
            const uint32_t b2 = smb + (uint32_t)((s + 2) % 3) * STAGE_SZ;
            issue_stage<LDA, LDB, BTRANS>(A, B, (s + 2) * 64, b2, b2 + 16384, tid);
        }
        const uint32_t bc = smb + (uint32_t)(s % 3) * STAGE_SZ;
        compute_stage<BTRANS>(bc, bc + 16384, wm, wn, lane, acc);
    }
}

#define ZERO_ACC(acc)                             \
    float acc[4][4][4];                           \
    _Pragma("unroll") for (int i = 0; i < 4; i++) \
    _Pragma("unroll") for (int j = 0; j < 4; j++) \
    _Pragma("unroll") for (int c = 0; c < 4; c++) acc[i][j][c] = 0.0f;

// ---------------------------------------------------------------------------
// Kernel 0: fp32 -> fp16 conversions (q,k,v,Wq,Wk,Wv)
// ---------------------------------------------------------------------------
__global__ __launch_bounds__(512) void convert_kernel(
    const float* __restrict__ q, const float* __restrict__ k,
    const float* __restrict__ v, const float* __restrict__ Wq,
    const float* __restrict__ Wk, const float* __restrict__ Wv)
{
    const int z = blockIdx.z;
    const float* src;
    __half* dst;
    size_t n8;
    if (z == 0)      { src = q;  dst = g_qx; n8 = (size_t)MT * Dd / 8; }
    else if (z == 1) { src = k;  dst = g_kx; n8 = (size_t)MT * Dd / 8; }
    else if (z == 2) { src = v;  dst = g_vx; n8 = (size_t)MT * Dd / 8; }
    else if (z == 3) { src = Wq; dst = g_wq; n8 = (size_t)Dd * Dd / 8; }
    else if (z == 4) { src = Wk; dst = g_wk; n8 = (size_t)Dd * Dd / 8; }
    else             { src = Wv; dst = g_wv; n8 = (size_t)Dd * Dd / 8; }
    const size_t i = (size_t)blockIdx.x * 512 + threadIdx.x;
    if (i >= n8) return;
    const float4* s4 = (const float4*)src;
    float4 a = s4[i * 2], b = s4[i * 2 + 1];
    __half2 h[4];
    h[0] = __floats2half2_rn(a.x, a.y);
    h[1] = __floats2half2_rn(a.z, a.w);
    h[2] = __floats2half2_rn(b.x, b.y);
    h[3] = __floats2half2_rn(b.z, b.w);
    ((uint4*)dst)[i] = *(uint4*)h;
}

// ---------------------------------------------------------------------------
// Kernel 1: QKV projections. z selects GEMM. Output fp16 (+bias).
// ---------------------------------------------------------------------------
__global__ __launch_bounds__(NT, 3) void proj_hmma(
    const float* __restrict__ bq, const float* __restrict__ bk,
    const float* __restrict__ bv)
{
    extern __shared__ char sm[];
    const int m0 = blockIdx.x * 128, n0 = blockIdx.y * 64, z = blockIdx.z;
    const __half *X, *W;
    const float* bias;
    __half* C;
    if (z == 0)      { X = g_qx; W = g_wq; bias = bq; C = g_qp; }
    else if (z == 1) { X = g_kx; W = g_wk; bias = bk; C = g_kp; }
    else             { X = g_vx; W = g_wv; bias = bv; C = g_vp; }

    ZERO_ACC(acc);
    gemm_main<Dd, Dd, false>(X + (size_t)m0 * Dd, W + (size_t)n0 * Dd, Dd / 64, sm, acc);

    const int lane = threadIdx.x & 31, warp = threadIdx.x >> 5;
    const int wm = warp & 1, wn = warp >> 1, g = lane >> 2, tk = lane & 3;
#pragma unroll
    for (int mi = 0; mi < 4; mi++) {
        const int r0 = m0 + wm * 64 + mi * 16 + g;
#pragma unroll
        for (int ni = 0; ni < 4; ni++) {
            const int col = n0 + wn * 32 + ni * 8 + tk * 2;
            const float bx = bias[col], by = bias[col + 1];
            *(__half2*)&C[(size_t)r0 * Dd + col] =
                __floats2half2_rn(acc[mi][ni][0] + bx, acc[mi][ni][1] + by);
            *(__half2*)&C[(size_t)(r0 + 8) * Dd + col] =
                __floats2half2_rn(acc[mi][ni][2] + bx, acc[mi][ni][3] + by);
        }
    }
}

// ---------------------------------------------------------------------------
// Kernel 2: causal raw scores, fp32 logits out (/32).
// Above-diagonal tiles write the final fp32 zeros (streaming stores that
// overlap with the live GEMM CTAs); softmax then never touches j >= bound.
// ---------------------------------------------------------------------------
__global__ __launch_bounds__(NT, 3) void scores_hmma(float* __restrict__ attn) {
    const int m0 = blockIdx.x * 128, n0 = blockIdx.y * 64;
    const int b = blockIdx.z;
    float* C = attn + (size_t)b * Ss * Ss;

    if (n0 > m0 + 127) {
        // final zeros for this entirely-above-diagonal tile
        const float4 z4 = make_float4(0.f, 0.f, 0.f, 0.f);
        const int tid = threadIdx.x;
#pragma unroll
        for (int i = 0; i < 16; i++) {
            const int id = tid + i * NT;           // 0..2047
            const int row = id >> 4, c4 = id & 15; // 128 rows x 16 float4
            *(float4*)&C[(size_t)(m0 + row) * Ss + n0 + c4 * 4] = z4;
        }
        return;
    }

    extern __shared__ char sm[];
    const __half* A = g_qp + (size_t)b * Ss * Dd;
    const __half* B = g_kp + (size_t)b * Ss * Dd;

    ZERO_ACC(acc);
    gemm_main<Dd, Dd, false>(A + (size_t)m0 * Dd, B + (size_t)n0 * Dd, Dd / 64, sm, acc);

    const int lane = threadIdx.x & 31, warp = threadIdx.x >> 5;
    const int wm = warp & 1, wn = warp >> 1, g = lane >> 2, tk = lane & 3;
#pragma unroll
    for (int mi = 0; mi < 4; mi++) {
        const int r0 = m0 + wm * 64 + mi * 16 + g;
#pragma unroll
        for (int ni = 0; ni < 4; ni++) {
            const int col = n0 + wn * 32 + ni * 8 + tk * 2;
            *(float2*)&C[(size_t)r0 * Ss + col] =
                make_float2(acc[mi][ni][0] * INV_TEMP, acc[mi][ni][1] * INV_TEMP);
            *(float2*)&C[(size_t)(r0 + 8) * Ss + col] =
                make_float2(acc[mi][ni][2] * INV_TEMP, acc[mi][ni][3] * INV_TEMP);
        }
    }
}

// ---------------------------------------------------------------------------
// Kernel 3: causal row softmax (fp32 in-place + fp16 copy).
// Touches only j < bound; zeros beyond were written by scores' dead tiles.
// 256 threads, two float4 per thread; warp-shuffle reductions; __expf.
// ---------------------------------------------------------------------------
__global__ __launch_bounds__(256) void softmax_kernel(float* __restrict__ attn) {
    const int rix = blockIdx.x;
    const int b = rix / Ss;
    const int i = rix % Ss;
    float* row = attn + (size_t)b * Ss * Ss + (size_t)i * Ss;
    __half2* rowh2 = (__half2*)(g_attn_h + (size_t)b * Ss * Ss + (size_t)i * Ss);
    const int tid = threadIdx.x;
    const int lane = tid & 31, wid = tid >> 5;
    const int valid = i + 1;
    const int bound = ((i >> 7) + 1) << 7;   // 128-aligned causal bound

    float4 x[2];
    float lmax = -3.0e38f;
#pragma unroll
    for (int it = 0; it < 2; it++) {
        const int j0 = (tid + it * 256) * 4;
        if (j0 < valid) {
            x[it] = *(const float4*)(row + j0);
            float* e = (float*)&x[it];
#pragma unroll
            for (int c = 0; c < 4; c++)
                if (j0 + c < valid) lmax = fmaxf(lmax, e[c]);
        } else {
            x[it] = make_float4(0.f, 0.f, 0.f, 0.f);
        }
    }

    __shared__ float sred[8];
#pragma unroll
    for (int o = 16; o > 0; o >>= 1)
        lmax = fmaxf(lmax, __shfl_xor_sync(0xFFFFFFFF, lmax, o));
    if (lane == 0) sred[wid] = lmax;
    __syncthreads();
    float mx = sred[0];
#pragma unroll
    for (int w = 1; w < 8; w++) mx = fmaxf(mx, sred[w]);

    float lsum = 0.0f;
#pragma unroll
    for (int it = 0; it < 2; it++) {
        const int j0 = (tid + it * 256) * 4;
        float* e = (float*)&x[it];
        if (j0 < valid) {
#pragma unroll
            for (int c = 0; c < 4; c++) {
                const float t = (j0 + c < valid) ? __expf(e[c] - mx) : 0.0f;
                e[c] = t;
                lsum += t;
            }
        }
    }
#pragma unroll
    for (int o = 16; o > 0; o >>= 1)
        lsum += __shfl_xor_sync(0xFFFFFFFF, lsum, o);
    __syncthreads();              // protect sred reuse
    if (lane == 0) sred[wid] = lsum;
    __syncthreads();
    float tot = sred[0];
#pragma unroll
    for (int w = 1; w < 8; w++) tot += sred[w];
    const float inv = 1.0f / tot;

#pragma unroll
    for (int it = 0; it < 2; it++) {
        const int j4 = tid + it * 256;
        const int j0 = j4 * 4;
        if (j0 >= bound) continue;   // beyond bound: zeros already in place
        float* e = (float*)&x[it];
        float4 y;
        if (j0 < valid) {
            y.x = e[0] * inv; y.y = e[1] * inv; y.z = e[2] * inv; y.w = e[3] * inv;
        } else {
            y = make_float4(0.f, 0.f, 0.f, 0.f);
        }
        *(float4*)(row + j0) = y;
        rowh2[j4 * 2]     = __floats2half2_rn(y.x, y.y);
        rowh2[j4 * 2 + 1] = __floats2half2_rn(y.z, y.w);
    }
}

// ---------------------------------------------------------------------------
// Kernel 4: output = attn_h @ vp (NN GEMM via trans-ldmatrix B), fp32 out.
// K truncated at m0+128. Heaviest panels (large m0) scheduled FIRST (LPT).
// ---------------------------------------------------------------------------
__global__ __launch_bounds__(NT, 3) void av_hmma(float* __restrict__ out) {
    extern __shared__ char sm[];
    const int m0 = (Ss / 128 - 1 - (int)blockIdx.x) * 128;   // descending work
    const int n0 = blockIdx.y * 64;
    const int b = blockIdx.z;
    const __half* A = g_attn_h + (size_t)b * Ss * Ss;
    const __half* B = g_vp + (size_t)b * Ss * Dd + n0;  // [t][d], col offset n0
    float* C = out + (size_t)b * Ss * Dd;

    ZERO_ACC(acc);
    gemm_main<Ss, Dd, true>(A + (size_t)m0 * Ss, B, (m0 + 128) / 64, sm, acc);

    const int lane = threadIdx.x & 31, warp = threadIdx.x >> 5;
    const int wm = warp & 1, wn = warp >> 1, g = lane >> 2, tk = lane & 3;
#pragma unroll
    for (int mi = 0; mi < 4; mi++) {
        const int r0 = m0 + wm * 64 + mi * 16 + g;
#pragma unroll
        for (int ni = 0; ni < 4; ni++) {
            const int col = n0 + wn * 32 + ni * 8 + tk * 2;
            *(float2*)&C[(size_t)r0 * Dd + col] =
                make_float2(acc[mi][ni][0], acc[mi][ni][1]);
            *(float2*)&C[(size_t)(r0 + 8) * Dd + col] =
                make_float2(acc[mi][ni][2], acc[mi][ni][3]);
        }
    }
}

// ---------------------------------------------------------------------------
// Host launch. d_out = [output (B*S*D) | attn (B*S*S)] fp32.
// ---------------------------------------------------------------------------
extern "C" void kernel_launch(void* const* d_in, const int* in_sizes, int n_in,
                              void* d_out, int out_size)
{
    const float* q  = (const float*)d_in[0];
    const float* k  = (const float*)d_in[1];
    const float* v  = (const float*)d_in[2];
    const float* Wq = (const float*)d_in[3];
    const float* bq = (const float*)d_in[4];
    const float* Wk = (const float*)d_in[5];
    const float* bk = (const float*)d_in[6];
    const float* Wv = (const float*)d_in[7];
    const float* bv = (const float*)d_in[8];

    float* out  = (float*)d_out;
    float* outO = out;                         // [B,S,D]
    float* attn = out + (size_t)Bb * Ss * Dd;  // [B,S,S]

    cudaFuncSetAttribute(proj_hmma, cudaFuncAttributeMaxDynamicSharedMemorySize, SMEMSZ);
    cudaFuncSetAttribute(scores_hmma, cudaFuncAttributeMaxDynamicSharedMemorySize, SMEMSZ);
    cudaFuncSetAttribute(av_hmma, cudaFuncAttributeMaxDynamicSharedMemorySize, SMEMSZ);

    // 0) fp32 -> fp16 conversions
    convert_kernel<<<dim3(4096, 1, 6), 512>>>(q, k, v, Wq, Wk, Wv);

    // 1) QKV projections
    proj_hmma<<<dim3(MT / 128, Dd / 64, 3), NT, SMEMSZ>>>(bq, bk, bv);

    // 2) causal raw scores (+ final zeros from above-diagonal tiles)
    scores_hmma<<<dim3(Ss / 128, Ss / 64, Bb), NT, SMEMSZ>>>(attn);

    // 3) softmax (fp32 in-place + fp16 copy, bounded)
    softmax_kernel<<<MT, 256>>>(attn);

    // 4) output = attn @ vp (NN, trans-ldmatrix B; heavy panels first)
    av_hmma<<<dim3(Ss / 128, Dd / 64, Bb), NT, SMEMSZ>>>(outO);
}

// round 17
// speedup vs baseline: 1.0523x; 1.0124x over previous
#include <cuda_runtime.h>
#include <cuda_fp16.h>
#include <stdint.h>

// Problem constants
static constexpr int Bb = 8;
static constexpr int Ss = 2048;
static constexpr int Dd = 1024;
static constexpr int MT = Bb * Ss;
static constexpr float INV_TEMP = 1.0f / 32.0f;

// GEMM tiling: 128(M) x 64(N) x 64(K) stages, 3-stage cp.async pipeline,
// ONE barrier per stage. 128 threads / 4 warps per CTA, warp tile 64x32,
// 3 CTAs per SM (216 KB smem).
#define STAGE_SZ 24576           // A tile 16KB + B tile 8KB
#define SMEMSZ   73728           // 3 stages
#define NT 128

// fp16 scratch (device globals: allocation-free)
__device__ __half g_qx[(size_t)MT * Dd];
__device__ __half g_kx[(size_t)MT * Dd];
__device__ __half g_vx[(size_t)MT * Dd];
__device__ __half g_wq[(size_t)Dd * Dd];
__device__ __half g_wk[(size_t)Dd * Dd];
__device__ __half g_wv[(size_t)Dd * Dd];
__device__ __half g_qp[(size_t)MT * Dd];
__device__ __half g_kp[(size_t)MT * Dd];
__device__ __half g_vp[(size_t)MT * Dd];
__device__ __half g_attn_h[(size_t)Bb * Ss * Ss];  // fp16 softmax output

// ---------------------------------------------------------------------------
// PTX helpers
// ---------------------------------------------------------------------------
__device__ __forceinline__ uint32_t smem_u32(const void* p) {
    return (uint32_t)__cvta_generic_to_shared(p);
}
__device__ __forceinline__ uint32_t swz(uint32_t off) {
    return off ^ ((off >> 3) & 0x70);   // SW128 for 128B rows
}
__device__ __forceinline__ void cp16(uint32_t dst, const void* src) {
    asm volatile("cp.async.cg.shared.global [%0], [%1], 16;" :: "r"(dst), "l"(src));
}
__device__ __forceinline__ void ldsm4(uint32_t& r0, uint32_t& r1,
                                      uint32_t& r2, uint32_t& r3, uint32_t addr) {
    asm volatile("ldmatrix.sync.aligned.m8n8.x4.shared.b16 {%0,%1,%2,%3}, [%4];"
                 : "=r"(r0), "=r"(r1), "=r"(r2), "=r"(r3) : "r"(addr));
}
__device__ __forceinline__ void ldsm4t(uint32_t& r0, uint32_t& r1,
                                       uint32_t& r2, uint32_t& r3, uint32_t addr) {
    asm volatile("ldmatrix.sync.aligned.m8n8.x4.trans.shared.b16 {%0,%1,%2,%3}, [%4];"
                 : "=r"(r0), "=r"(r1), "=r"(r2), "=r"(r3) : "r"(addr));
}
__device__ __forceinline__ void mma16816(float c[4], const uint32_t a[4],
                                         const uint32_t b[2]) {
    asm volatile(
        "mma.sync.aligned.m16n8k16.row.col.f32.f16.f16.f32 "
        "{%0,%1,%2,%3}, {%4,%5,%6,%7}, {%8,%9}, {%0,%1,%2,%3};"
        : "+f"(c[0]), "+f"(c[1]), "+f"(c[2]), "+f"(c[3])
        : "r"(a[0]), "r"(a[1]), "r"(a[2]), "r"(a[3]), "r"(b[0]), "r"(b[1]));
}

// ---------------------------------------------------------------------------
// Stage loader. A: 128 rows x 64 k-cols (row-major, advance cols by kt).
// B (NT):     64 n-rows x 64 k-cols (row-major [n][k], advance cols by kt).
// B (TRANS):  64 k-rows x 64 n-cols (row-major [k][n], advance ROWS by kt).
// ---------------------------------------------------------------------------
template <int LDA, int LDB, bool BTRANS>
__device__ __forceinline__ void issue_stage(
    const __half* __restrict__ A, const __half* __restrict__ B, int kt,
    uint32_t abase, uint32_t bbase, int tid)
{
#pragma unroll
    for (int i = 0; i < 8; i++) {
        const int id = tid + i * NT;
        const int row = id >> 3, cc = id & 7;
        cp16(abase + swz(row * 128 + cc * 16), A + (size_t)row * LDA + kt + cc * 8);
    }
#pragma unroll
    for (int i = 0; i < 4; i++) {
        const int id = tid + i * NT;
        const int row = id >> 3, cc = id & 7;
        const __half* src = BTRANS
            ? B + (size_t)(kt + row) * LDB + cc * 8
            : B + (size_t)row * LDB + kt + cc * 8;
        cp16(bbase + swz(row * 128 + cc * 16), src);
    }
    asm volatile("cp.async.commit_group;");
}

// ---------------------------------------------------------------------------
// Compute one 128x64x64 stage. Warp grid 2(m) x 2(n); warp tile 64x32.
// ---------------------------------------------------------------------------
template <bool BTRANS>
__device__ __forceinline__ void compute_stage(
    uint32_t abase, uint32_t bbase, int wm, int wn, int lane,
    float acc[4][4][4])
{
    const int a_row = wm * 64 + (lane & 15);
    const int a_col = (lane >> 4) * 8;
    // NT path lane mapping
    const int b_row = wn * 32 + ((lane >> 4) * 8) + (lane & 7);
    const int b_col = ((lane >> 3) & 1) * 8;
    // TRANS path lane mapping: row = k (lane&15), col-block = (lane>>4)*8
    const int bt_k = lane & 15;
    const int bt_n = wn * 32 + (lane >> 4) * 8;
#pragma unroll
    for (int ks = 0; ks < 4; ks++) {
        uint32_t af[4][4], bf[4][2];
#pragma unroll
        for (int mi = 0; mi < 4; mi++)
            ldsm4(af[mi][0], af[mi][1], af[mi][2], af[mi][3],
                  abase + swz(((a_row + mi * 16) << 7) + (ks * 16 + a_col) * 2));
#pragma unroll
        for (int nj = 0; nj < 2; nj++) {
            if (BTRANS) {
                ldsm4t(bf[2 * nj][0], bf[2 * nj][1],
                       bf[2 * nj + 1][0], bf[2 * nj + 1][1],
                       bbase + swz(((ks * 16 + bt_k) << 7) + (bt_n + nj * 16) * 2));
            } else {
                ldsm4(bf[2 * nj][0], bf[2 * nj][1],
                      bf[2 * nj + 1][0], bf[2 * nj + 1][1],
                      bbase + swz(((b_row + nj * 16) << 7) + (ks * 16 + b_col) * 2));
            }
        }
#pragma unroll
        for (int mi = 0; mi < 4; mi++)
#pragma unroll
            for (int ni = 0; ni < 4; ni++)
                mma16816(acc[mi][ni], af[mi], bf[ni]);
    }
}

// ---------------------------------------------------------------------------
// Full GEMM mainloop. 3-stage pipeline, ONE barrier per stage, 2 stages of
// loads in flight.
// ---------------------------------------------------------------------------
template <int LDA, int LDB, bool BTRANS>
__device__ __forceinline__ void gemm_main(
    const __half* __restrict__ A, const __half* __restrict__ B,
    int nk, char* sm, float acc[4][4][4])
{
    const uint32_t smb = smem_u32(sm);
    const int tid = threadIdx.x, lane = tid & 31, warp = tid >> 5;
    const int wm = warp & 1, wn = warp >> 1;

    issue_stage<LDA, LDB, BTRANS>(A, B, 0, smb, smb + 16384, tid);
    if (nk > 1) {
        const uint32_t b1 = smb + STAGE_SZ;
        issue_stage<LDA, LDB, BTRANS>(A, B, 64, b1, b1 + 16384, tid);
    }

    for (int s = 0; s < nk; s++) {
        if (s + 1 < nk) asm volatile("cp.async.wait_group 1;");
        else            asm volatile("cp.async.wait_group 0;");
        __syncthreads();   // stage s visible; all warps done with compute(s-1)
        if (s + 2 < nk) {
            const uint32_t b2 = smb + (uint32_t)((s + 2) % 3) * STAGE_SZ;
            issue_stage<LDA, LDB, BTRANS>(A, B, (s + 2) * 64, b2, b2 + 16384, tid);
        }
        const uint32_t bc = smb + (uint32_t)(s % 3) * STAGE_SZ;
        compute_stage<BTRANS>(bc, bc + 16384, wm, wn, lane, acc);
    }
}

#define ZERO_ACC(acc)                             \
    float acc[4][4][4];                           \
    _Pragma("unroll") for (int i = 0; i < 4; i++) \
    _Pragma("unroll") for (int j = 0; j < 4; j++) \
    _Pragma("unroll") for (int c = 0; c < 4; c++) acc[i][j][c] = 0.0f;

// ---------------------------------------------------------------------------
// Kernel 0a/0b: fp32 -> fp16 conversions, split into {q,k,Wq,Wk} and {v,Wv}
// ---------------------------------------------------------------------------
__device__ __forceinline__ void convert_body(const float* src, __half* dst,
                                             size_t n8, size_t i) {
    if (i >= n8) return;
    const float4* s4 = (const float4*)src;
    float4 a = s4[i * 2], b = s4[i * 2 + 1];
    __half2 h[4];
    h[0] = __floats2half2_rn(a.x, a.y);
    h[1] = __floats2half2_rn(a.z, a.w);
    h[2] = __floats2half2_rn(b.x, b.y);
    h[3] = __floats2half2_rn(b.z, b.w);
    ((uint4*)dst)[i] = *(uint4*)h;
}

__global__ __launch_bounds__(512) void convert_qk(
    const float* __restrict__ q, const float* __restrict__ k,
    const float* __restrict__ Wq, const float* __restrict__ Wk)
{
    const int z = blockIdx.z;
    const float* src;
    __half* dst;
    size_t n8;
    if (z == 0)      { src = q;  dst = g_qx; n8 = (size_t)MT * Dd / 8; }
    else if (z == 1) { src = k;  dst = g_kx; n8 = (size_t)MT * Dd / 8; }
    else if (z == 2) { src = Wq; dst = g_wq; n8 = (size_t)Dd * Dd / 8; }
    else             { src = Wk; dst = g_wk; n8 = (size_t)Dd * Dd / 8; }
    convert_body(src, dst, n8, (size_t)blockIdx.x * 512 + threadIdx.x);
}

__global__ __launch_bounds__(512) void convert_v(
    const float* __restrict__ v, const float* __restrict__ Wv)
{
    const int z = blockIdx.z;
    const float* src;
    __half* dst;
    size_t n8;
    if (z == 0) { src = v;  dst = g_vx; n8 = (size_t)MT * Dd / 8; }
    else        { src = Wv; dst = g_wv; n8 = (size_t)Dd * Dd / 8; }
    convert_body(src, dst, n8, (size_t)blockIdx.x * 512 + threadIdx.x);
}

// ---------------------------------------------------------------------------
// Kernel 1: QKV projections. zbase+blockIdx.z selects GEMM. fp16 out (+bias).
// ---------------------------------------------------------------------------
__global__ __launch_bounds__(NT, 3) void proj_hmma(
    const float* __restrict__ bq, const float* __restrict__ bk,
    const float* __restrict__ bv, int zbase)
{
    extern __shared__ char sm[];
    const int m0 = blockIdx.x * 128, n0 = blockIdx.y * 64;
    const int z = zbase + blockIdx.z;
    const __half *X, *W;
    const float* bias;
    __half* C;
    if (z == 0)      { X = g_qx; W = g_wq; bias = bq; C = g_qp; }
    else if (z == 1) { X = g_kx; W = g_wk; bias = bk; C = g_kp; }
    else             { X = g_vx; W = g_wv; bias = bv; C = g_vp; }

    ZERO_ACC(acc);
    gemm_main<Dd, Dd, false>(X + (size_t)m0 * Dd, W + (size_t)n0 * Dd, Dd / 64, sm, acc);

    const int lane = threadIdx.x & 31, warp = threadIdx.x >> 5;
    const int wm = warp & 1, wn = warp >> 1, g = lane >> 2, tk = lane & 3;
#pragma unroll
    for (int mi = 0; mi < 4; mi++) {
        const int r0 = m0 + wm * 64 + mi * 16 + g;
#pragma unroll
        for (int ni = 0; ni < 4; ni++) {
            const int col = n0 + wn * 32 + ni * 8 + tk * 2;
            const float bx = bias[col], by = bias[col + 1];
            *(__half2*)&C[(size_t)r0 * Dd + col] =
                __floats2half2_rn(acc[mi][ni][0] + bx, acc[mi][ni][1] + by);
            *(__half2*)&C[(size_t)(r0 + 8) * Dd + col] =
                __floats2half2_rn(acc[mi][ni][2] + bx, acc[mi][ni][3] + by);
        }
    }
}

// ---------------------------------------------------------------------------
// Kernel 2: causal raw scores, fp32 logits out (/32).
// Above-diagonal tiles write the final fp32 zeros.
// ---------------------------------------------------------------------------
__global__ __launch_bounds__(NT, 3) void scores_hmma(float* __restrict__ attn) {
    const int m0 = blockIdx.x * 128, n0 = blockIdx.y * 64;
    const int b = blockIdx.z;
    float* C = attn + (size_t)b * Ss * Ss;

    if (n0 > m0 + 127) {
        const float4 z4 = make_float4(0.f, 0.f, 0.f, 0.f);
        const int tid = threadIdx.x;
#pragma unroll
        for (int i = 0; i < 16; i++) {
            const int id = tid + i * NT;           // 0..2047
            const int row = id >> 4, c4 = id & 15; // 128 rows x 16 float4
            *(float4*)&C[(size_t)(m0 + row) * Ss + n0 + c4 * 4] = z4;
        }
        return;
    }

    extern __shared__ char sm[];
    const __half* A = g_qp + (size_t)b * Ss * Dd;
    const __half* B = g_kp + (size_t)b * Ss * Dd;

    ZERO_ACC(acc);
    gemm_main<Dd, Dd, false>(A + (size_t)m0 * Dd, B + (size_t)n0 * Dd, Dd / 64, sm, acc);

    const int lane = threadIdx.x & 31, warp = threadIdx.x >> 5;
    const int wm = warp & 1, wn = warp >> 1, g = lane >> 2, tk = lane & 3;
#pragma unroll
    for (int mi = 0; mi < 4; mi++) {
        const int r0 = m0 + wm * 64 + mi * 16 + g;
#pragma unroll
        for (int ni = 0; ni < 4; ni++) {
            const int col = n0 + wn * 32 + ni * 8 + tk * 2;
            *(float2*)&C[(size_t)r0 * Ss + col] =
                make_float2(acc[mi][ni][0] * INV_TEMP, acc[mi][ni][1] * INV_TEMP);
            *(float2*)&C[(size_t)(r0 + 8) * Ss + col] =
                make_float2(acc[mi][ni][2] * INV_TEMP, acc[mi][ni][3] * INV_TEMP);
        }
    }
}

// ---------------------------------------------------------------------------
// Kernel 3: causal row softmax (fp32 in-place + fp16 copy), bounded.
// ---------------------------------------------------------------------------
__global__ __launch_bounds__(256) void softmax_kernel(float* __restrict__ attn) {
    const int rix = blockIdx.x;
    const int b = rix / Ss;
    const int i = rix % Ss;
    float* row = attn + (size_t)b * Ss * Ss + (size_t)i * Ss;
    __half2* rowh2 = (__half2*)(g_attn_h + (size_t)b * Ss * Ss + (size_t)i * Ss);
    const int tid = threadIdx.x;
    const int lane = tid & 31, wid = tid >> 5;
    const int valid = i + 1;
    const int bound = ((i >> 7) + 1) << 7;   // 128-aligned causal bound

    float4 x[2];
    float lmax = -3.0e38f;
#pragma unroll
    for (int it = 0; it < 2; it++) {
        const int j0 = (tid + it * 256) * 4;
        if (j0 < valid) {
            x[it] = *(const float4*)(row + j0);
            float* e = (float*)&x[it];
#pragma unroll
            for (int c = 0; c < 4; c++)
                if (j0 + c < valid) lmax = fmaxf(lmax, e[c]);
        } else {
            x[it] = make_float4(0.f, 0.f, 0.f, 0.f);
        }
    }

    __shared__ float sred[8];
#pragma unroll
    for (int o = 16; o > 0; o >>= 1)
        lmax = fmaxf(lmax, __shfl_xor_sync(0xFFFFFFFF, lmax, o));
    if (lane == 0) sred[wid] = lmax;
    __syncthreads();
    float mx = sred[0];
#pragma unroll
    for (int w = 1; w < 8; w++) mx = fmaxf(mx, sred[w]);

    float lsum = 0.0f;
#pragma unroll
    for (int it = 0; it < 2; it++) {
        const int j0 = (tid + it * 256) * 4;
        float* e = (float*)&x[it];
        if (j0 < valid) {
#pragma unroll
            for (int c = 0; c < 4; c++) {
                const float t = (j0 + c < valid) ? __expf(e[c] - mx) : 0.0f;
                e[c] = t;
                lsum += t;
            }
        }
    }
#pragma unroll
    for (int o = 16; o > 0; o >>= 1)
        lsum += __shfl_xor_sync(0xFFFFFFFF, lsum, o);
    __syncthreads();              // protect sred reuse
    if (lane == 0) sred[wid] = lsum;
    __syncthreads();
    float tot = sred[0];
#pragma unroll
    for (int w = 1; w < 8; w++) tot += sred[w];
    const float inv = 1.0f / tot;

#pragma unroll
    for (int it = 0; it < 2; it++) {
        const int j4 = tid + it * 256;
        const int j0 = j4 * 4;
        if (j0 >= bound) continue;   // beyond bound: zeros already in place
        float* e = (float*)&x[it];
        float4 y;
        if (j0 < valid) {
            y.x = e[0] * inv; y.y = e[1] * inv; y.z = e[2] * inv; y.w = e[3] * inv;
        } else {
            y = make_float4(0.f, 0.f, 0.f, 0.f);
        }
        *(float4*)(row + j0) = y;
        rowh2[j4 * 2]     = __floats2half2_rn(y.x, y.y);
        rowh2[j4 * 2 + 1] = __floats2half2_rn(y.z, y.w);
    }
}

// ---------------------------------------------------------------------------
// Kernel 4: output = attn_h @ vp (NN GEMM via trans-ldmatrix B), fp32 out.
// K truncated at m0+128. Heaviest panels (large m0) scheduled FIRST (LPT).
// ---------------------------------------------------------------------------
__global__ __launch_bounds__(NT, 3) void av_hmma(float* __restrict__ out) {
    extern __shared__ char sm[];
    const int m0 = (Ss / 128 - 1 - (int)blockIdx.x) * 128;   // descending work
    const int n0 = blockIdx.y * 64;
    const int b = blockIdx.z;
    const __half* A = g_attn_h + (size_t)b * Ss * Ss;
    const __half* B = g_vp + (size_t)b * Ss * Dd + n0;  // [t][d], col offset n0
    float* C = out + (size_t)b * Ss * Dd;

    ZERO_ACC(acc);
    gemm_main<Ss, Dd, true>(A + (size_t)m0 * Ss, B, (m0 + 128) / 64, sm, acc);

    const int lane = threadIdx.x & 31, warp = threadIdx.x >> 5;
    const int wm = warp & 1, wn = warp >> 1, g = lane >> 2, tk = lane & 3;
#pragma unroll
    for (int mi = 0; mi < 4; mi++) {
        const int r0 = m0 + wm * 64 + mi * 16 + g;
#pragma unroll
        for (int ni = 0; ni < 4; ni++) {
            const int col = n0 + wn * 32 + ni * 8 + tk * 2;
            *(float2*)&C[(size_t)r0 * Dd + col] =
                make_float2(acc[mi][ni][0], acc[mi][ni][1]);
            *(float2*)&C[(size_t)(r0 + 8) * Dd + col] =
                make_float2(acc[mi][ni][2], acc[mi][ni][3]);
        }
    }
}

// ---------------------------------------------------------------------------
// Host launch. d_out = [output (B*S*D) | attn (B*S*S)] fp32.
// Fork-join: side stream handles convert_v + proj_v overlapping with the
// scores/softmax window on the main stream; joined before av.
// ---------------------------------------------------------------------------
extern "C" void kernel_launch(void* const* d_in, const int* in_sizes, int n_in,
                              void* d_out, int out_size)
{
    const float* q  = (const float*)d_in[0];
    const float* k  = (const float*)d_in[1];
    const float* v  = (const float*)d_in[2];
    const float* Wq = (const float*)d_in[3];
    const float* bq = (const float*)d_in[4];
    const float* Wk = (const float*)d_in[5];
    const float* bk = (const float*)d_in[6];
    const float* Wv = (const float*)d_in[7];
    const float* bv = (const float*)d_in[8];

    float* out  = (float*)d_out;
    float* outO = out;                         // [B,S,D]
    float* attn = out + (size_t)Bb * Ss * Dd;  // [B,S,S]

    static cudaStream_t s2 = nullptr;
    static cudaEvent_t evFork = nullptr, evJoin = nullptr;
    static bool attrs_set = false;
    if (s2 == nullptr) {
        cudaStreamCreateWithFlags(&s2, cudaStreamNonBlocking);
        cudaEventCreateWithFlags(&evFork, cudaEventDisableTiming);
        cudaEventCreateWithFlags(&evJoin, cudaEventDisableTiming);
    }
    if (!attrs_set) {
        cudaFuncSetAttribute(proj_hmma, cudaFuncAttributeMaxDynamicSharedMemorySize, SMEMSZ);
        cudaFuncSetAttribute(scores_hmma, cudaFuncAttributeMaxDynamicSharedMemorySize, SMEMSZ);
        cudaFuncSetAttribute(av_hmma, cudaFuncAttributeMaxDynamicSharedMemorySize, SMEMSZ);
        attrs_set = true;
    }

    // main stream: q/k conversions
    convert_qk<<<dim3(4096, 1, 4), 512>>>(q, k, Wq, Wk);

    // fork side stream
    cudaEventRecord(evFork, 0);
    cudaStreamWaitEvent(s2, evFork, 0);

    // side stream: v conversion + v projection (overlaps scores/softmax)
    convert_v<<<dim3(4096, 1, 2), 512, 0, s2>>>(v, Wv);
    proj_hmma<<<dim3(MT / 128, Dd / 64, 1), NT, SMEMSZ, s2>>>(bq, bk, bv, 2);
    cudaEventRecord(evJoin, s2);

    // main stream: q/k projections -> scores -> softmax
    proj_hmma<<<dim3(MT / 128, Dd / 64, 2), NT, SMEMSZ>>>(bq, bk, bv, 0);
    scores_hmma<<<dim3(Ss / 128, Ss / 64, Bb), NT, SMEMSZ>>>(attn);
    softmax_kernel<<<MT, 256>>>(attn);

    // join: av needs vp + attn_h
    cudaStreamWaitEvent(0, evJoin, 0);
    av_hmma<<<dim3(Ss / 128, Dd / 64, Bb), NT, SMEMSZ>>>(outO);
}